// round 5
// baseline (speedup 1.0000x reference)
#include <cuda_runtime.h>
#include <math.h>

#define B_  8
#define L_  128
#define H_  768
#define M_  (B_ * L_)      // 1024 rows
#define LL_ (L_ * L_)      // 16384 pairs per batch

// ---------------- scratch (no allocations allowed) ----------------
__device__ float g_A[M_ * H_];          // seq @ W1[:H] + b1   (3 MB)
__device__ float g_C[M_ * H_];          // seq @ W1[H:]        (3 MB)
__device__ float g_se[2 * M_];          // per-row start/end CE
__device__ float g_span_partial[128];   // per-block span BCE partials
__device__ unsigned int g_counter;      // last-block counter (self-resetting)

// ---------------- f32x2 packed helpers ----------------
typedef unsigned long long ull;

__device__ __forceinline__ ull dup2(float v) {
    ull r; asm("mov.b64 %0, {%1, %2};" : "=l"(r) : "f"(v), "f"(v)); return r;
}
__device__ __forceinline__ ull pk2(float lo, float hi) {
    ull r; asm("mov.b64 %0, {%1, %2};" : "=l"(r) : "f"(lo), "f"(hi)); return r;
}
__device__ __forceinline__ void upk2(ull v, float& lo, float& hi) {
    asm("mov.b64 {%0, %1}, %2;" : "=f"(lo), "=f"(hi) : "l"(v));
}
__device__ __forceinline__ ull fma2_(ull a, ull b, ull c) {
    ull d; asm("fma.rn.f32x2 %0, %1, %2, %3;" : "=l"(d) : "l"(a), "l"(b), "l"(c)); return d;
}
__device__ __forceinline__ ull mul2_(ull a, ull b) {
    ull d; asm("mul.rn.f32x2 %0, %1, %2;" : "=l"(d) : "l"(a), "l"(b)); return d;
}
__device__ __forceinline__ ull add2_(ull a, ull b) {
    ull d; asm("add.rn.f32x2 %0, %1, %2;" : "=l"(d) : "l"(a), "l"(b)); return d;
}
__device__ __forceinline__ float rcp_(float x) {
    float r; asm("rcp.approx.f32 %0, %1;" : "=f"(r) : "f"(x)); return r;
}
__device__ __forceinline__ float ex2_(float x) {
    float r; asm("ex2.approx.f32 %0, %1;" : "=f"(r) : "f"(x)); return r;
}

// hoisted constants for gelu2 (built once per thread, outside hot loops)
struct GK {
    ull irt2, p, one, a5, a4, a3, a2, a1, nl2e, half;
};
__device__ __forceinline__ GK make_gk() {
    GK k;
    k.irt2 = dup2(0.70710678118654752f);
    k.p    = dup2(0.3275911f);
    k.one  = dup2(1.0f);
    k.a5   = dup2(-1.061405429f);
    k.a4   = dup2(1.453152027f);
    k.a3   = dup2(-1.421413741f);
    k.a2   = dup2(0.284496736f);
    k.a1   = dup2(-0.254829592f);
    k.nl2e = dup2(-1.4426950408889634f);
    k.half = dup2(0.5f);
    return k;
}

// packed exact-GELU, copysign-free: gelu(x) = 0.5x + 0.5|x|*erf(|x|/sqrt2)
// erf via A&S 7.1.26 with sign-flipped coefficients (|eps| <= 1.5e-7)
__device__ __forceinline__ ull gelu2(ull x, const GK& k) {
    ull ax = x & 0x7FFFFFFF7FFFFFFFULL;
    ull z  = mul2_(ax, k.irt2);
    ull d  = fma2_(k.p, z, k.one);
    float dl, dh; upk2(d, dl, dh);
    ull t = pk2(rcp_(dl), rcp_(dh));
    ull p = fma2_(k.a5, t, k.a4);
    p = fma2_(p, t, k.a3);
    p = fma2_(p, t, k.a2);
    p = fma2_(p, t, k.a1);
    p = mul2_(p, t);                       // pn = -poly
    ull zz  = mul2_(z, z);
    ull arg = mul2_(zz, k.nl2e);           // -z^2 * log2(e)
    float al, ah; upk2(arg, al, ah);
    ull e = pk2(ex2_(al), ex2_(ah));
    ull erf = fma2_(p, e, k.one);          // erf(|x|/sqrt2) >= 0
    ull hax = mul2_(ax, k.half);
    return fma2_(hax, erf, mul2_(x, k.half));
}

// ---------------- fused GEMM: [A|C] = seq(1024x768) @ W1-derived (768x1536) ---
// 64x64 tile per CTA, 64 threads, 8x8 outputs per thread (as 4 m-pairs x 8 cols).
// B staged in smem PRE-DUPLICATED as f32x2 pairs -> no dup MOVs in inner loop.
__global__ void __launch_bounds__(64) gemm_kernel(
    const float* __restrict__ seq, const float* __restrict__ W1,
    const float* __restrict__ b1)
{
    __shared__ __align__(16) float As[16][68];    // k-major, row stride 272B
    __shared__ __align__(16) ull   Bs2[16][66];   // dup'd pairs, row stride 528B

    int tid = threadIdx.x;
    int tx = tid & 7, ty = tid >> 3;
    int m0 = blockIdx.y << 6;            // 16 m-tiles
    int n0 = blockIdx.x << 6;            // 24 n-tiles
    int isC = (n0 >= H_);
    const float* Bbase = W1 + (isC ? (H_ * H_ + (n0 - H_)) : n0);

    if (blockIdx.x == 0 && blockIdx.y == 0 && tid == 0) g_counter = 0u;

    int bk = tid & 15;                   // B loader: k row 0..15
    int bn = (tid >> 4) << 4;            // n segment 0,16,32,48

    ull acc[4][8];
#pragma unroll
    for (int p = 0; p < 4; p++)
#pragma unroll
        for (int c = 0; c < 8; c++) acc[p][c] = 0ULL;

    for (int k0 = 0; k0 < H_; k0 += 16) {
        // load A: thread tid owns row m0+tid, 16 k values
        const float* arow = seq + (m0 + tid) * H_ + k0;
        float4 a0 = *(const float4*)(arow);
        float4 a1 = *(const float4*)(arow + 4);
        float4 a2 = *(const float4*)(arow + 8);
        float4 a3 = *(const float4*)(arow + 12);
        As[0][tid] = a0.x;  As[1][tid] = a0.y;  As[2][tid] = a0.z;  As[3][tid] = a0.w;
        As[4][tid] = a1.x;  As[5][tid] = a1.y;  As[6][tid] = a1.z;  As[7][tid] = a1.w;
        As[8][tid] = a2.x;  As[9][tid] = a2.y;  As[10][tid] = a2.z; As[11][tid] = a2.w;
        As[12][tid] = a3.x; As[13][tid] = a3.y; As[14][tid] = a3.z; As[15][tid] = a3.w;
        // load B: row k0+bk, 16 n values, store duplicated
        const float* brow = Bbase + (k0 + bk) * H_ + bn;
#pragma unroll
        for (int q = 0; q < 4; q++) {
            float4 bv = *(const float4*)(brow + (q << 2));
            Bs2[bk][bn + (q << 2) + 0] = dup2(bv.x);
            Bs2[bk][bn + (q << 2) + 1] = dup2(bv.y);
            Bs2[bk][bn + (q << 2) + 2] = dup2(bv.z);
            Bs2[bk][bn + (q << 2) + 3] = dup2(bv.w);
        }
        __syncthreads();
#pragma unroll
        for (int k = 0; k < 16; k++) {
            ulonglong2 aA = *(const ulonglong2*)(&As[k][ty << 3]);
            ulonglong2 aB = *(const ulonglong2*)(&As[k][(ty << 3) + 4]);
            ull ap0 = aA.x, ap1 = aA.y, ap2 = aB.x, ap3 = aB.y;
            ulonglong2 b01 = *(const ulonglong2*)(&Bs2[k][(tx << 3) + 0]);
            ulonglong2 b23 = *(const ulonglong2*)(&Bs2[k][(tx << 3) + 2]);
            ulonglong2 b45 = *(const ulonglong2*)(&Bs2[k][(tx << 3) + 4]);
            ulonglong2 b67 = *(const ulonglong2*)(&Bs2[k][(tx << 3) + 6]);
            ull bv0 = b01.x, bv1 = b01.y, bv2 = b23.x, bv3 = b23.y;
            ull bv4 = b45.x, bv5 = b45.y, bv6 = b67.x, bv7 = b67.y;
            acc[0][0] = fma2_(ap0, bv0, acc[0][0]);
            acc[0][1] = fma2_(ap0, bv1, acc[0][1]);
            acc[0][2] = fma2_(ap0, bv2, acc[0][2]);
            acc[0][3] = fma2_(ap0, bv3, acc[0][3]);
            acc[0][4] = fma2_(ap0, bv4, acc[0][4]);
            acc[0][5] = fma2_(ap0, bv5, acc[0][5]);
            acc[0][6] = fma2_(ap0, bv6, acc[0][6]);
            acc[0][7] = fma2_(ap0, bv7, acc[0][7]);
            acc[1][0] = fma2_(ap1, bv0, acc[1][0]);
            acc[1][1] = fma2_(ap1, bv1, acc[1][1]);
            acc[1][2] = fma2_(ap1, bv2, acc[1][2]);
            acc[1][3] = fma2_(ap1, bv3, acc[1][3]);
            acc[1][4] = fma2_(ap1, bv4, acc[1][4]);
            acc[1][5] = fma2_(ap1, bv5, acc[1][5]);
            acc[1][6] = fma2_(ap1, bv6, acc[1][6]);
            acc[1][7] = fma2_(ap1, bv7, acc[1][7]);
            acc[2][0] = fma2_(ap2, bv0, acc[2][0]);
            acc[2][1] = fma2_(ap2, bv1, acc[2][1]);
            acc[2][2] = fma2_(ap2, bv2, acc[2][2]);
            acc[2][3] = fma2_(ap2, bv3, acc[2][3]);
            acc[2][4] = fma2_(ap2, bv4, acc[2][4]);
            acc[2][5] = fma2_(ap2, bv5, acc[2][5]);
            acc[2][6] = fma2_(ap2, bv6, acc[2][6]);
            acc[2][7] = fma2_(ap2, bv7, acc[2][7]);
            acc[3][0] = fma2_(ap3, bv0, acc[3][0]);
            acc[3][1] = fma2_(ap3, bv1, acc[3][1]);
            acc[3][2] = fma2_(ap3, bv2, acc[3][2]);
            acc[3][3] = fma2_(ap3, bv3, acc[3][3]);
            acc[3][4] = fma2_(ap3, bv4, acc[3][4]);
            acc[3][5] = fma2_(ap3, bv5, acc[3][5]);
            acc[3][6] = fma2_(ap3, bv6, acc[3][6]);
            acc[3][7] = fma2_(ap3, bv7, acc[3][7]);
        }
        __syncthreads();
    }

    int nc = n0 + (tx << 3);
    float bb[8];
#pragma unroll
    for (int c = 0; c < 8; c++) bb[c] = 0.0f;
    if (!isC) {
        float4 v0 = *(const float4*)(b1 + nc);
        float4 v1 = *(const float4*)(b1 + nc + 4);
        bb[0] = v0.x; bb[1] = v0.y; bb[2] = v0.z; bb[3] = v0.w;
        bb[4] = v1.x; bb[5] = v1.y; bb[6] = v1.z; bb[7] = v1.w;
    }
    int colbase = isC ? (nc - H_) : nc;
    float* dst = isC ? g_C : g_A;
#pragma unroll
    for (int p = 0; p < 4; p++) {
        float lo[8], hi[8];
#pragma unroll
        for (int c = 0; c < 8; c++) upk2(acc[p][c], lo[c], hi[c]);
        int mr = m0 + (ty << 3) + (p << 1);
        float4 o;
        o.x = lo[0] + bb[0]; o.y = lo[1] + bb[1]; o.z = lo[2] + bb[2]; o.w = lo[3] + bb[3];
        *(float4*)(dst + mr * H_ + colbase) = o;
        o.x = lo[4] + bb[4]; o.y = lo[5] + bb[5]; o.z = lo[6] + bb[6]; o.w = lo[7] + bb[7];
        *(float4*)(dst + mr * H_ + colbase + 4) = o;
        o.x = hi[0] + bb[0]; o.y = hi[1] + bb[1]; o.z = hi[2] + bb[2]; o.w = hi[3] + bb[3];
        *(float4*)(dst + (mr + 1) * H_ + colbase) = o;
        o.x = hi[4] + bb[4]; o.y = hi[5] + bb[5]; o.z = hi[6] + bb[6]; o.w = hi[7] + bb[7];
        *(float4*)(dst + (mr + 1) * H_ + colbase + 4) = o;
    }
}

// ---------------- start/end CE: one block per token row ----------------
__global__ void __launch_bounds__(128) se_kernel(
    const float* __restrict__ seq,
    const float* __restrict__ Ws, const float* __restrict__ bs,
    const float* __restrict__ We, const float* __restrict__ be,
    const int* __restrict__ spos, const int* __restrict__ epos)
{
    int m = blockIdx.x;
    int tid = threadIdx.x;
    const float* row = seq + m * H_;
    float s0 = 0.f, s1 = 0.f, e0 = 0.f, e1 = 0.f;
    for (int h = tid; h < H_; h += 128) {
        float x = row[h];
        float2 ws = *(const float2*)(Ws + 2 * h);
        float2 we = *(const float2*)(We + 2 * h);
        s0 = fmaf(x, ws.x, s0);
        s1 = fmaf(x, ws.y, s1);
        e0 = fmaf(x, we.x, e0);
        e1 = fmaf(x, we.y, e1);
    }
#pragma unroll
    for (int o = 16; o; o >>= 1) {
        s0 += __shfl_down_sync(0xffffffffu, s0, o);
        s1 += __shfl_down_sync(0xffffffffu, s1, o);
        e0 += __shfl_down_sync(0xffffffffu, e0, o);
        e1 += __shfl_down_sync(0xffffffffu, e1, o);
    }
    __shared__ float buf[4][4];
    int w = tid >> 5, lane = tid & 31;
    if (lane == 0) { buf[w][0] = s0; buf[w][1] = s1; buf[w][2] = e0; buf[w][3] = e1; }
    __syncthreads();
    if (tid == 0) {
        s0 = buf[0][0] + buf[1][0] + buf[2][0] + buf[3][0] + bs[0];
        s1 = buf[0][1] + buf[1][1] + buf[2][1] + buf[3][1] + bs[1];
        e0 = buf[0][2] + buf[1][2] + buf[2][2] + buf[3][2] + be[0];
        e1 = buf[0][3] + buf[1][3] + buf[2][3] + buf[3][3] + be[1];
        float mx  = fmaxf(s0, s1);
        float lse = mx + logf(expf(s0 - mx) + expf(s1 - mx));
        g_se[m] = lse - (spos[m] ? s1 : s0);
        mx  = fmaxf(e0, e1);
        lse = mx + logf(expf(e0 - mx) + expf(e1 - mx));
        g_se[M_ + m] = lse - (epos[m] ? e1 : e0);
    }
}

// ---------------- span BCE: 32x32 (i,j) tile, 512 threads, h split in halves --
__global__ void __launch_bounds__(512) span_kernel(
    const int* __restrict__ spanp, const float* __restrict__ w2,
    const float* __restrict__ b2, float* __restrict__ out)
{
    __shared__ __align__(16) float sAt[2][64][34]; // transposed A: [half][h][i]
    __shared__ __align__(16) float sC[2][32][67];  // C: [half][j][h] (67 = conflict-free pad)
    __shared__ ull   sW2[2][64];       // pre-dup'd w2
    __shared__ ull   part[2][256];     // half-1 partial accumulators
    __shared__ float red[512];
    __shared__ int   isLast;

    int tid = threadIdx.x;
    int g   = tid >> 8;                // h-half 0/1
    int t   = tid & 255;
    int tx = t & 15, ty = t >> 4;
    int b = blockIdx.z;
    int i0 = blockIdx.y << 5;
    int j0 = blockIdx.x << 5;
    const float* Abase = g_A + (b * L_ + i0) * H_ + g * 384;
    const float* Cbase = g_C + (b * L_ + j0) * H_ + g * 384;

    const GK gk = make_gk();

    int il = ty << 1, jl = tx << 1;
    ull acc0 = 0ULL, acc1 = 0ULL;

    for (int hc = 0; hc < 384; hc += 64) {
        {
            int row = t >> 3;                  // 0..31
            int c0  = (t & 7) << 3;            // 0..56
            float4 va0 = *(const float4*)(Abase + row * H_ + hc + c0);
            float4 va1 = *(const float4*)(Abase + row * H_ + hc + c0 + 4);
            sAt[g][c0 + 0][row] = va0.x; sAt[g][c0 + 1][row] = va0.y;
            sAt[g][c0 + 2][row] = va0.z; sAt[g][c0 + 3][row] = va0.w;
            sAt[g][c0 + 4][row] = va1.x; sAt[g][c0 + 5][row] = va1.y;
            sAt[g][c0 + 6][row] = va1.z; sAt[g][c0 + 7][row] = va1.w;
            float4 vc0 = *(const float4*)(Cbase + row * H_ + hc + c0);
            float4 vc1 = *(const float4*)(Cbase + row * H_ + hc + c0 + 4);
            sC[g][row][c0 + 0] = vc0.x; sC[g][row][c0 + 1] = vc0.y;
            sC[g][row][c0 + 2] = vc0.z; sC[g][row][c0 + 3] = vc0.w;
            sC[g][row][c0 + 4] = vc1.x; sC[g][row][c0 + 5] = vc1.y;
            sC[g][row][c0 + 6] = vc1.z; sC[g][row][c0 + 7] = vc1.w;
        }
        if (t < 64) sW2[g][t] = dup2(w2[g * 384 + hc + t]);
        __syncthreads();
#pragma unroll 4
        for (int h = 0; h < 64; h++) {
            ull aP = *(const ull*)(&sAt[g][h][il]);
            ull c0 = dup2(sC[g][jl][h]);
            ull c1 = dup2(sC[g][jl + 1][h]);
            ull wd = sW2[g][h];
            acc0 = fma2_(gelu2(add2_(aP, c0), gk), wd, acc0);
            acc1 = fma2_(gelu2(add2_(aP, c1), gk), wd, acc1);
        }
        __syncthreads();
    }

    if (g) { part[0][t] = acc0; part[1][t] = acc1; }
    __syncthreads();

    float bsum = 0.f;
    if (!g) {
        acc0 = add2_(acc0, part[0][t]);
        acc1 = add2_(acc1, part[1][t]);
        float b2v = b2[0];
        const int* zb = spanp + b * LL_;
        int i = i0 + il, j = j0 + jl;
        float lg[2][2];
        upk2(acc0, lg[0][0], lg[1][0]);   // (i0,j0), (i1,j0)
        upk2(acc1, lg[0][1], lg[1][1]);   // (i0,j1), (i1,j1)
#pragma unroll
        for (int r = 0; r < 2; r++)
#pragma unroll
            for (int s = 0; s < 2; s++) {
                float sg = lg[r][s] + b2v;
                float z  = (float)zb[(i + r) * L_ + (j + s)];
                bsum += fmaxf(sg, 0.f) - sg * z + log1pf(__expf(-fabsf(sg)));
            }
    }

    red[tid] = bsum;
    __syncthreads();
    for (int o = 256; o; o >>= 1) {
        if (tid < o) red[tid] += red[tid + o];
        __syncthreads();
    }
    int bid = (blockIdx.z << 4) + (blockIdx.y << 2) + blockIdx.x;
    if (tid == 0) {
        g_span_partial[bid] = red[0];
        __threadfence();
        unsigned int old = atomicAdd(&g_counter, 1u);
        isLast = (old == 127u);
    }
    __syncthreads();

    if (isLast) {
        __threadfence();
        float se = 0.f;
        for (int q = tid; q < 2 * M_; q += 512) se += g_se[q];
        float sp = (tid < 128) ? g_span_partial[tid] : 0.f;
        red[tid] = se * (1.0f / (float)M_) + sp * (1.0f / (float)(B_ * LL_));
        __syncthreads();
        for (int o = 256; o; o >>= 1) {
            if (tid < o) red[tid] += red[tid + o];
            __syncthreads();
        }
        if (tid == 0) { out[0] = red[0]; g_counter = 0u; }
    }
}

// ---------------- launch ----------------
extern "C" void kernel_launch(void* const* d_in, const int* in_sizes, int n_in,
                              void* d_out, int out_size)
{
    const float* seq   = (const float*)d_in[0];
    const int*   spos  = (const int*)  d_in[1];
    const int*   epos  = (const int*)  d_in[2];
    const int*   spanp = (const int*)  d_in[3];
    const float* Ws    = (const float*)d_in[4];
    const float* bs    = (const float*)d_in[5];
    const float* We    = (const float*)d_in[6];
    const float* be    = (const float*)d_in[7];
    const float* W1    = (const float*)d_in[8];
    const float* b1    = (const float*)d_in[9];
    const float* w2    = (const float*)d_in[10];
    const float* b2    = (const float*)d_in[11];
    float* out = (float*)d_out;

    gemm_kernel<<<dim3(24, 16), 64>>>(seq, W1, b1);
    se_kernel<<<M_, 128>>>(seq, Ws, bs, We, be, spos, epos);
    span_kernel<<<dim3(4, 4, 8), 512>>>(spanp, w2, b2, out);
}

// round 6
// speedup vs baseline: 1.7745x; 1.7745x over previous
#include <cuda_runtime.h>
#include <mma.h>
#include <math.h>

using namespace nvcuda;

#define B_  8
#define L_  128
#define H_  768
#define M_  (B_ * L_)      // 1024 rows
#define LL_ (L_ * L_)      // 16384 pairs per batch

// ---------------- scratch (no allocations allowed) ----------------
__device__ float g_A[M_ * H_];          // seq @ W1[:H]        (3 MB)  (bias folded in span)
__device__ float g_C[M_ * H_];          // seq @ W1[H:]        (3 MB)
__device__ float g_se[2 * M_];          // per-row start/end CE
__device__ float g_span_partial[128];   // per-block span BCE partials
__device__ unsigned int g_counter;      // last-block counter (self-resetting)

// ---------------- f32x2 packed helpers ----------------
typedef unsigned long long ull;

__device__ __forceinline__ ull dup2(float v) {
    ull r; asm("mov.b64 %0, {%1, %2};" : "=l"(r) : "f"(v), "f"(v)); return r;
}
__device__ __forceinline__ ull pk2(float lo, float hi) {
    ull r; asm("mov.b64 %0, {%1, %2};" : "=l"(r) : "f"(lo), "f"(hi)); return r;
}
__device__ __forceinline__ void upk2(ull v, float& lo, float& hi) {
    asm("mov.b64 {%0, %1}, %2;" : "=f"(lo), "=f"(hi) : "l"(v));
}
__device__ __forceinline__ ull fma2_(ull a, ull b, ull c) {
    ull d; asm("fma.rn.f32x2 %0, %1, %2, %3;" : "=l"(d) : "l"(a), "l"(b), "l"(c)); return d;
}
__device__ __forceinline__ ull mul2_(ull a, ull b) {
    ull d; asm("mul.rn.f32x2 %0, %1, %2;" : "=l"(d) : "l"(a), "l"(b)); return d;
}
__device__ __forceinline__ ull add2_(ull a, ull b) {
    ull d; asm("add.rn.f32x2 %0, %1, %2;" : "=l"(d) : "l"(a), "l"(b)); return d;
}
__device__ __forceinline__ float rcp_(float x) {
    float r; asm("rcp.approx.f32 %0, %1;" : "=f"(r) : "f"(x)); return r;
}
__device__ __forceinline__ float ex2_(float x) {
    float r; asm("ex2.approx.f32 %0, %1;" : "=f"(r) : "f"(x)); return r;
}

// hoisted constants for gelu2 (built once per thread, outside hot loops)
struct GK {
    ull irt2, p, one, a5, a4, a3, a2, a1, nl2e, half;
};
__device__ __forceinline__ GK make_gk() {
    GK k;
    k.irt2 = dup2(0.70710678118654752f);
    k.p    = dup2(0.3275911f);
    k.one  = dup2(1.0f);
    k.a5   = dup2(-1.061405429f);
    k.a4   = dup2(1.453152027f);
    k.a3   = dup2(-1.421413741f);
    k.a2   = dup2(0.284496736f);
    k.a1   = dup2(-0.254829592f);
    k.nl2e = dup2(-1.4426950408889634f);
    k.half = dup2(0.5f);
    return k;
}

// packed exact-GELU, copysign-free: gelu(x) = 0.5x + 0.5|x|*erf(|x|/sqrt2)
// erf via A&S 7.1.26 with sign-flipped coefficients (|eps| <= 1.5e-7)
__device__ __forceinline__ ull gelu2(ull x, const GK& k) {
    ull ax = x & 0x7FFFFFFF7FFFFFFFULL;
    ull z  = mul2_(ax, k.irt2);
    ull d  = fma2_(k.p, z, k.one);
    float dl, dh; upk2(d, dl, dh);
    ull t = pk2(rcp_(dl), rcp_(dh));
    ull p = fma2_(k.a5, t, k.a4);
    p = fma2_(p, t, k.a3);
    p = fma2_(p, t, k.a2);
    p = fma2_(p, t, k.a1);
    p = mul2_(p, t);                       // pn = -poly
    ull zz  = mul2_(z, z);
    ull arg = mul2_(zz, k.nl2e);           // -z^2 * log2(e)
    float al, ah; upk2(arg, al, ah);
    ull e = pk2(ex2_(al), ex2_(ah));
    ull erf = fma2_(p, e, k.one);          // erf(|x|/sqrt2) >= 0
    ull hax = mul2_(ax, k.half);
    return fma2_(hax, erf, mul2_(x, k.half));
}

// ---------------- tf32 wmma GEMM: [A|C] = seq(1024x768) @ W1 (768x1536) ------
// CTA: 128(m) x 64(n) tile, 256 threads = 8 warps in 4(m) x 2(n) layout,
// each warp 32x32 = 2x2 wmma m16n16k8 tiles. k staged in chunks of 32.
__global__ void __launch_bounds__(256) gemm_kernel(
    const float* __restrict__ seq, const float* __restrict__ W1)
{
    __shared__ __align__(16) float As[128][36];  // m x k-chunk, ld 36 (144B, 16B mult)
    __shared__ __align__(16) float Bs[32][68];   // k x n-chunk, ld 68 (272B, 16B mult)

    int tid = threadIdx.x;
    int wid = tid >> 5;
    int wm = wid >> 1;                 // 0..3  (m position, 32 rows each)
    int wn = wid & 1;                  // 0..1  (n position, 32 cols each)
    int m0 = blockIdx.y << 7;          // 8 m-tiles
    int n0 = blockIdx.x << 6;          // 24 n-tiles
    int isC = (n0 >= H_);
    const float* Bbase = W1 + (isC ? (H_ * H_ + (n0 - H_)) : n0);

    if (blockIdx.x == 0 && blockIdx.y == 0 && tid == 0) g_counter = 0u;

    wmma::fragment<wmma::accumulator, 16, 16, 8, float> acc[2][2];
#pragma unroll
    for (int i = 0; i < 2; i++)
#pragma unroll
        for (int j = 0; j < 2; j++) wmma::fill_fragment(acc[i][j], 0.0f);

    // staging maps
    int a_row = tid >> 1;              // 0..127
    int a_c16 = (tid & 1) << 4;        // 0 or 16
    int b_k   = tid >> 3;              // 0..31
    int b_n8  = (tid & 7) << 3;        // 0..56

    for (int k0 = 0; k0 < H_; k0 += 32) {
        // stage A: 128 x 32
        const float* arow = seq + (m0 + a_row) * H_ + k0 + a_c16;
#pragma unroll
        for (int q = 0; q < 4; q++) {
            float4 v = *(const float4*)(arow + (q << 2));
            As[a_row][a_c16 + (q << 2) + 0] = wmma::__float_to_tf32(v.x);
            As[a_row][a_c16 + (q << 2) + 1] = wmma::__float_to_tf32(v.y);
            As[a_row][a_c16 + (q << 2) + 2] = wmma::__float_to_tf32(v.z);
            As[a_row][a_c16 + (q << 2) + 3] = wmma::__float_to_tf32(v.w);
        }
        // stage B: 32 x 64
        const float* brow = Bbase + (k0 + b_k) * H_ + b_n8;
#pragma unroll
        for (int q = 0; q < 2; q++) {
            float4 v = *(const float4*)(brow + (q << 2));
            Bs[b_k][b_n8 + (q << 2) + 0] = wmma::__float_to_tf32(v.x);
            Bs[b_k][b_n8 + (q << 2) + 1] = wmma::__float_to_tf32(v.y);
            Bs[b_k][b_n8 + (q << 2) + 2] = wmma::__float_to_tf32(v.z);
            Bs[b_k][b_n8 + (q << 2) + 3] = wmma::__float_to_tf32(v.w);
        }
        __syncthreads();
#pragma unroll
        for (int sk = 0; sk < 4; sk++) {
            wmma::fragment<wmma::matrix_a, 16, 16, 8, wmma::precision::tf32, wmma::row_major> af[2];
            wmma::fragment<wmma::matrix_b, 16, 16, 8, wmma::precision::tf32, wmma::row_major> bf[2];
            wmma::load_matrix_sync(af[0], &As[(wm << 5) +  0][sk << 3], 36);
            wmma::load_matrix_sync(af[1], &As[(wm << 5) + 16][sk << 3], 36);
            wmma::load_matrix_sync(bf[0], &Bs[sk << 3][(wn << 5) +  0], 68);
            wmma::load_matrix_sync(bf[1], &Bs[sk << 3][(wn << 5) + 16], 68);
#pragma unroll
            for (int i = 0; i < 2; i++)
#pragma unroll
                for (int j = 0; j < 2; j++)
                    wmma::mma_sync(acc[i][j], af[i], bf[j], acc[i][j]);
        }
        __syncthreads();
    }

    float* dst = isC ? g_C : g_A;
    int colbase = (isC ? (n0 - H_) : n0) + (wn << 5);
    int rowbase = m0 + (wm << 5);
#pragma unroll
    for (int i = 0; i < 2; i++)
#pragma unroll
        for (int j = 0; j < 2; j++)
            wmma::store_matrix_sync(dst + (rowbase + (i << 4)) * H_ + colbase + (j << 4),
                                    acc[i][j], H_, wmma::mem_row_major);
}

// ---------------- start/end CE: one block per token row ----------------
__global__ void __launch_bounds__(128) se_kernel(
    const float* __restrict__ seq,
    const float* __restrict__ Ws, const float* __restrict__ bs,
    const float* __restrict__ We, const float* __restrict__ be,
    const int* __restrict__ spos, const int* __restrict__ epos)
{
    int m = blockIdx.x;
    int tid = threadIdx.x;
    const float* row = seq + m * H_;
    float s0 = 0.f, s1 = 0.f, e0 = 0.f, e1 = 0.f;
    for (int h = tid; h < H_; h += 128) {
        float x = row[h];
        float2 ws = *(const float2*)(Ws + 2 * h);
        float2 we = *(const float2*)(We + 2 * h);
        s0 = fmaf(x, ws.x, s0);
        s1 = fmaf(x, ws.y, s1);
        e0 = fmaf(x, we.x, e0);
        e1 = fmaf(x, we.y, e1);
    }
#pragma unroll
    for (int o = 16; o; o >>= 1) {
        s0 += __shfl_down_sync(0xffffffffu, s0, o);
        s1 += __shfl_down_sync(0xffffffffu, s1, o);
        e0 += __shfl_down_sync(0xffffffffu, e0, o);
        e1 += __shfl_down_sync(0xffffffffu, e1, o);
    }
    __shared__ float buf[4][4];
    int w = tid >> 5, lane = tid & 31;
    if (lane == 0) { buf[w][0] = s0; buf[w][1] = s1; buf[w][2] = e0; buf[w][3] = e1; }
    __syncthreads();
    if (tid == 0) {
        s0 = buf[0][0] + buf[1][0] + buf[2][0] + buf[3][0] + bs[0];
        s1 = buf[0][1] + buf[1][1] + buf[2][1] + buf[3][1] + bs[1];
        e0 = buf[0][2] + buf[1][2] + buf[2][2] + buf[3][2] + be[0];
        e1 = buf[0][3] + buf[1][3] + buf[2][3] + buf[3][3] + be[1];
        float mx  = fmaxf(s0, s1);
        float lse = mx + logf(expf(s0 - mx) + expf(s1 - mx));
        g_se[m] = lse - (spos[m] ? s1 : s0);
        mx  = fmaxf(e0, e1);
        lse = mx + logf(expf(e0 - mx) + expf(e1 - mx));
        g_se[M_ + m] = lse - (epos[m] ? e1 : e0);
    }
}

// ---------------- span BCE: 32x32 (i,j) tile, 512 threads, h split in halves --
// b1 is folded in here (added to A during staging).
__global__ void __launch_bounds__(512) span_kernel(
    const int* __restrict__ spanp, const float* __restrict__ w2,
    const float* __restrict__ b2, const float* __restrict__ b1,
    float* __restrict__ out)
{
    __shared__ __align__(16) float sAt[2][64][34]; // transposed A: [half][h][i]
    __shared__ __align__(16) float sC[2][32][67];  // C: [half][j][h]
    __shared__ ull   sW2[2][64];       // pre-dup'd w2
    __shared__ ull   part[2][256];     // half-1 partial accumulators
    __shared__ float red[512];
    __shared__ int   isLast;

    int tid = threadIdx.x;
    int g   = tid >> 8;                // h-half 0/1
    int t   = tid & 255;
    int tx = t & 15, ty = t >> 4;
    int b = blockIdx.z;
    int i0 = blockIdx.y << 5;
    int j0 = blockIdx.x << 5;
    const float* Abase = g_A + (b * L_ + i0) * H_ + g * 384;
    const float* Cbase = g_C + (b * L_ + j0) * H_ + g * 384;
    const float* b1g   = b1 + g * 384;

    const GK gk = make_gk();

    int il = ty << 1, jl = tx << 1;
    ull acc0 = 0ULL, acc1 = 0ULL;

    for (int hc = 0; hc < 384; hc += 64) {
        {
            int row = t >> 3;                  // 0..31
            int c0  = (t & 7) << 3;            // 0..56
            float4 vb0 = *(const float4*)(b1g + hc + c0);
            float4 vb1 = *(const float4*)(b1g + hc + c0 + 4);
            float4 va0 = *(const float4*)(Abase + row * H_ + hc + c0);
            float4 va1 = *(const float4*)(Abase + row * H_ + hc + c0 + 4);
            sAt[g][c0 + 0][row] = va0.x + vb0.x; sAt[g][c0 + 1][row] = va0.y + vb0.y;
            sAt[g][c0 + 2][row] = va0.z + vb0.z; sAt[g][c0 + 3][row] = va0.w + vb0.w;
            sAt[g][c0 + 4][row] = va1.x + vb1.x; sAt[g][c0 + 5][row] = va1.y + vb1.y;
            sAt[g][c0 + 6][row] = va1.z + vb1.z; sAt[g][c0 + 7][row] = va1.w + vb1.w;
            float4 vc0 = *(const float4*)(Cbase + row * H_ + hc + c0);
            float4 vc1 = *(const float4*)(Cbase + row * H_ + hc + c0 + 4);
            sC[g][row][c0 + 0] = vc0.x; sC[g][row][c0 + 1] = vc0.y;
            sC[g][row][c0 + 2] = vc0.z; sC[g][row][c0 + 3] = vc0.w;
            sC[g][row][c0 + 4] = vc1.x; sC[g][row][c0 + 5] = vc1.y;
            sC[g][row][c0 + 6] = vc1.z; sC[g][row][c0 + 7] = vc1.w;
        }
        if (t < 64) sW2[g][t] = dup2(w2[g * 384 + hc + t]);
        __syncthreads();
#pragma unroll 4
        for (int h = 0; h < 64; h++) {
            ull aP = *(const ull*)(&sAt[g][h][il]);
            ull c0 = dup2(sC[g][jl][h]);
            ull c1 = dup2(sC[g][jl + 1][h]);
            ull wd = sW2[g][h];
            acc0 = fma2_(gelu2(add2_(aP, c0), gk), wd, acc0);
            acc1 = fma2_(gelu2(add2_(aP, c1), gk), wd, acc1);
        }
        __syncthreads();
    }

    if (g) { part[0][t] = acc0; part[1][t] = acc1; }
    __syncthreads();

    float bsum = 0.f;
    if (!g) {
        acc0 = add2_(acc0, part[0][t]);
        acc1 = add2_(acc1, part[1][t]);
        float b2v = b2[0];
        const int* zb = spanp + b * LL_;
        int i = i0 + il, j = j0 + jl;
        float lg[2][2];
        upk2(acc0, lg[0][0], lg[1][0]);   // (i0,j0), (i1,j0)
        upk2(acc1, lg[0][1], lg[1][1]);   // (i0,j1), (i1,j1)
#pragma unroll
        for (int r = 0; r < 2; r++)
#pragma unroll
            for (int s = 0; s < 2; s++) {
                float sg = lg[r][s] + b2v;
                float z  = (float)zb[(i + r) * L_ + (j + s)];
                bsum += fmaxf(sg, 0.f) - sg * z + log1pf(__expf(-fabsf(sg)));
            }
    }

    red[tid] = bsum;
    __syncthreads();
    for (int o = 256; o; o >>= 1) {
        if (tid < o) red[tid] += red[tid + o];
        __syncthreads();
    }
    int bid = (blockIdx.z << 4) + (blockIdx.y << 2) + blockIdx.x;
    if (tid == 0) {
        g_span_partial[bid] = red[0];
        __threadfence();
        unsigned int old = atomicAdd(&g_counter, 1u);
        isLast = (old == 127u);
    }
    __syncthreads();

    if (isLast) {
        __threadfence();
        float se = 0.f;
        for (int q = tid; q < 2 * M_; q += 512) se += g_se[q];
        float sp = (tid < 128) ? g_span_partial[tid] : 0.f;
        red[tid] = se * (1.0f / (float)M_) + sp * (1.0f / (float)(B_ * LL_));
        __syncthreads();
        for (int o = 256; o; o >>= 1) {
            if (tid < o) red[tid] += red[tid + o];
            __syncthreads();
        }
        if (tid == 0) { out[0] = red[0]; g_counter = 0u; }
    }
}

// ---------------- launch ----------------
extern "C" void kernel_launch(void* const* d_in, const int* in_sizes, int n_in,
                              void* d_out, int out_size)
{
    const float* seq   = (const float*)d_in[0];
    const int*   spos  = (const int*)  d_in[1];
    const int*   epos  = (const int*)  d_in[2];
    const int*   spanp = (const int*)  d_in[3];
    const float* Ws    = (const float*)d_in[4];
    const float* bs    = (const float*)d_in[5];
    const float* We    = (const float*)d_in[6];
    const float* be    = (const float*)d_in[7];
    const float* W1    = (const float*)d_in[8];
    const float* b1    = (const float*)d_in[9];
    const float* w2    = (const float*)d_in[10];
    const float* b2    = (const float*)d_in[11];
    float* out = (float*)d_out;

    gemm_kernel<<<dim3(24, 8), 256>>>(seq, W1);
    se_kernel<<<M_, 128>>>(seq, Ws, bs, We, be, spos, epos);
    span_kernel<<<dim3(4, 4, 8), 512>>>(spanp, w2, b2, b1, out);
}

// round 7
// speedup vs baseline: 2.0043x; 1.1295x over previous
#include <cuda_runtime.h>
#include <mma.h>
#include <math.h>

using namespace nvcuda;

#define B_  8
#define L_  128
#define H_  768
#define M_  (B_ * L_)      // 1024 rows
#define LL_ (L_ * L_)      // 16384 pairs per batch

// ---------------- scratch (no allocations allowed) ----------------
__device__ float g_A [M_ * H_];         // k-half-0 partial of seq @ W1[:H]; after combine: full A+b1
__device__ float g_A1[M_ * H_];         // k-half-1 partial
__device__ float g_C [M_ * H_];         // k-half-0 partial of seq @ W1[H:]; after combine: full C
__device__ float g_C1[M_ * H_];         // k-half-1 partial
__device__ float g_se[2 * M_];          // per-row start/end CE
__device__ float g_span_partial[128];   // per-block span BCE partials
__device__ unsigned int g_counter;      // last-block counter (self-resetting)

// ---------------- f32x2 packed helpers ----------------
typedef unsigned long long ull;

__device__ __forceinline__ ull dup2(float v) {
    ull r; asm("mov.b64 %0, {%1, %2};" : "=l"(r) : "f"(v), "f"(v)); return r;
}
__device__ __forceinline__ ull pk2(float lo, float hi) {
    ull r; asm("mov.b64 %0, {%1, %2};" : "=l"(r) : "f"(lo), "f"(hi)); return r;
}
__device__ __forceinline__ void upk2(ull v, float& lo, float& hi) {
    asm("mov.b64 {%0, %1}, %2;" : "=f"(lo), "=f"(hi) : "l"(v));
}
__device__ __forceinline__ ull fma2_(ull a, ull b, ull c) {
    ull d; asm("fma.rn.f32x2 %0, %1, %2, %3;" : "=l"(d) : "l"(a), "l"(b), "l"(c)); return d;
}
__device__ __forceinline__ ull mul2_(ull a, ull b) {
    ull d; asm("mul.rn.f32x2 %0, %1, %2;" : "=l"(d) : "l"(a), "l"(b)); return d;
}
__device__ __forceinline__ ull add2_(ull a, ull b) {
    ull d; asm("add.rn.f32x2 %0, %1, %2;" : "=l"(d) : "l"(a), "l"(b)); return d;
}
__device__ __forceinline__ float rcp_(float x) {
    float r; asm("rcp.approx.f32 %0, %1;" : "=f"(r) : "f"(x)); return r;
}

// hoisted constants for gelu2 (A&S 7.1.28: 1 rcp, no exp)
struct GK {
    ull irt2, one, negone, half, a1, a2, a3, a4, a5, a6;
};
__device__ __forceinline__ GK make_gk() {
    GK k;
    k.irt2   = dup2(0.70710678118654752f);
    k.one    = dup2(1.0f);
    k.negone = dup2(-1.0f);
    k.half   = dup2(0.5f);
    k.a1 = dup2(0.0705230784f);
    k.a2 = dup2(0.0422820123f);
    k.a3 = dup2(0.0092705272f);
    k.a4 = dup2(0.0001520143f);
    k.a5 = dup2(0.0002765672f);
    k.a6 = dup2(0.0000430638f);
    return k;
}

// packed GELU via A&S 7.1.28: erf(z) = 1 - (1+a1 z+...+a6 z^6)^-16, |eps|<=3e-7
// gelu(x) = 0.5x * (1 + erf(|x|/sqrt2) with x's sign)
__device__ __forceinline__ ull gelu2(ull x, const GK& k) {
    ull ax  = x & 0x7FFFFFFF7FFFFFFFULL;
    ull sgn = x & 0x8000000080000000ULL;
    ull z = mul2_(ax, k.irt2);
    ull u = fma2_(k.a6, z, k.a5);
    u = fma2_(u, z, k.a4);
    u = fma2_(u, z, k.a3);
    u = fma2_(u, z, k.a2);
    u = fma2_(u, z, k.a1);
    u = fma2_(u, z, k.one);
    ull u2  = mul2_(u, u);
    ull u4  = mul2_(u2, u2);
    ull u8  = mul2_(u4, u4);
    ull u16 = mul2_(u8, u8);
    float l, h; upk2(u16, l, h);
    ull r = pk2(rcp_(l), rcp_(h));
    ull erf = fma2_(r, k.negone, k.one);   // 1 - u^-16, in [0,1)
    erf |= sgn;                            // copysign(erf, x)
    ull hx = mul2_(x, k.half);
    return fma2_(hx, erf, hx);
}

// ---------------- tf32 wmma GEMM (k-split x2, register-prefetch pipeline) ----
// CTA: 128(m) x 64(n) tile over k-half of 384, 256 threads = 8 warps (4m x 2n),
// each warp 32x32 = 2x2 wmma m16n16k8. k staged in 12 chunks of 32, with the
// next chunk's LDG issued before the mma work so global latency overlaps.
__global__ void __launch_bounds__(256) gemm_kernel(
    const float* __restrict__ seq, const float* __restrict__ W1)
{
    __shared__ __align__(16) float As[128][36];
    __shared__ __align__(16) float Bs[32][68];

    int tid = threadIdx.x;
    int wid = tid >> 5;
    int wm = wid >> 1;                 // 0..3
    int wn = wid & 1;                  // 0..1
    int m0 = blockIdx.y << 7;          // 8 m-tiles
    int n0 = blockIdx.x << 6;          // 24 n-tiles
    int kz = (int)blockIdx.z * 384;    // k-half offset
    int isC = (n0 >= H_);
    const float* Bbase = W1 + (isC ? (H_ * H_ + (n0 - H_)) : n0);

    if (blockIdx.x == 0 && blockIdx.y == 0 && blockIdx.z == 0 && tid == 0) g_counter = 0u;

    wmma::fragment<wmma::accumulator, 16, 16, 8, float> acc[2][2];
#pragma unroll
    for (int i = 0; i < 2; i++)
#pragma unroll
        for (int j = 0; j < 2; j++) wmma::fill_fragment(acc[i][j], 0.0f);

    int a_row = tid >> 1;              // 0..127
    int a_c16 = (tid & 1) << 4;        // 0 or 16
    int b_k   = tid >> 3;              // 0..31
    int b_n8  = (tid & 7) << 3;        // 0..56

    const float* arow = seq + (m0 + a_row) * H_ + kz + a_c16;
    const float* brow = Bbase + (kz + b_k) * H_ + b_n8;

    float4 pa[4], pb[2];
#pragma unroll
    for (int q = 0; q < 4; q++) pa[q] = *(const float4*)(arow + (q << 2));
#pragma unroll
    for (int q = 0; q < 2; q++) pb[q] = *(const float4*)(brow + (q << 2));

    for (int it = 0; it < 12; it++) {
        // commit prefetched regs to smem (with tf32 rounding)
#pragma unroll
        for (int q = 0; q < 4; q++) {
            As[a_row][a_c16 + (q << 2) + 0] = wmma::__float_to_tf32(pa[q].x);
            As[a_row][a_c16 + (q << 2) + 1] = wmma::__float_to_tf32(pa[q].y);
            As[a_row][a_c16 + (q << 2) + 2] = wmma::__float_to_tf32(pa[q].z);
            As[a_row][a_c16 + (q << 2) + 3] = wmma::__float_to_tf32(pa[q].w);
        }
#pragma unroll
        for (int q = 0; q < 2; q++) {
            Bs[b_k][b_n8 + (q << 2) + 0] = wmma::__float_to_tf32(pb[q].x);
            Bs[b_k][b_n8 + (q << 2) + 1] = wmma::__float_to_tf32(pb[q].y);
            Bs[b_k][b_n8 + (q << 2) + 2] = wmma::__float_to_tf32(pb[q].z);
            Bs[b_k][b_n8 + (q << 2) + 3] = wmma::__float_to_tf32(pb[q].w);
        }
        __syncthreads();
        // prefetch next chunk (overlaps with mma below)
        if (it < 11) {
            arow += 32;
            brow += 32 * H_;
#pragma unroll
            for (int q = 0; q < 4; q++) pa[q] = *(const float4*)(arow + (q << 2));
#pragma unroll
            for (int q = 0; q < 2; q++) pb[q] = *(const float4*)(brow + (q << 2));
        }
#pragma unroll
        for (int sk = 0; sk < 4; sk++) {
            wmma::fragment<wmma::matrix_a, 16, 16, 8, wmma::precision::tf32, wmma::row_major> af[2];
            wmma::fragment<wmma::matrix_b, 16, 16, 8, wmma::precision::tf32, wmma::row_major> bf[2];
            wmma::load_matrix_sync(af[0], &As[(wm << 5) +  0][sk << 3], 36);
            wmma::load_matrix_sync(af[1], &As[(wm << 5) + 16][sk << 3], 36);
            wmma::load_matrix_sync(bf[0], &Bs[sk << 3][(wn << 5) +  0], 68);
            wmma::load_matrix_sync(bf[1], &Bs[sk << 3][(wn << 5) + 16], 68);
#pragma unroll
            for (int i = 0; i < 2; i++)
#pragma unroll
                for (int j = 0; j < 2; j++)
                    wmma::mma_sync(acc[i][j], af[i], bf[j], acc[i][j]);
        }
        __syncthreads();
    }

    float* dst = blockIdx.z ? (isC ? g_C1 : g_A1) : (isC ? g_C : g_A);
    int colbase = (isC ? (n0 - H_) : n0) + (wn << 5);
    int rowbase = m0 + (wm << 5);
#pragma unroll
    for (int i = 0; i < 2; i++)
#pragma unroll
        for (int j = 0; j < 2; j++)
            wmma::store_matrix_sync(dst + (rowbase + (i << 4)) * H_ + colbase + (j << 4),
                                    acc[i][j], H_, wmma::mem_row_major);
}

// ---------------- combine k-split partials; fold b1 into A --------------------
__global__ void __launch_bounds__(256) combine_kernel(const float* __restrict__ b1)
{
    int idx = blockIdx.x * 256 + threadIdx.x;
    if (blockIdx.x < 768) {
        int f = idx << 2;
        float4 a0 = *(const float4*)(g_A  + f);
        float4 a1 = *(const float4*)(g_A1 + f);
        float4 bb = *(const float4*)(b1 + (f % H_));
        float4 o;
        o.x = a0.x + a1.x + bb.x; o.y = a0.y + a1.y + bb.y;
        o.z = a0.z + a1.z + bb.z; o.w = a0.w + a1.w + bb.w;
        *(float4*)(g_A + f) = o;
    } else {
        int f = (idx - 768 * 256) << 2;
        float4 c0 = *(const float4*)(g_C  + f);
        float4 c1 = *(const float4*)(g_C1 + f);
        float4 o;
        o.x = c0.x + c1.x; o.y = c0.y + c1.y;
        o.z = c0.z + c1.z; o.w = c0.w + c1.w;
        *(float4*)(g_C + f) = o;
    }
}

// ---------------- start/end CE: one block per token row ----------------
__global__ void __launch_bounds__(128) se_kernel(
    const float* __restrict__ seq,
    const float* __restrict__ Ws, const float* __restrict__ bs,
    const float* __restrict__ We, const float* __restrict__ be,
    const int* __restrict__ spos, const int* __restrict__ epos)
{
    int m = blockIdx.x;
    int tid = threadIdx.x;
    const float* row = seq + m * H_;
    float s0 = 0.f, s1 = 0.f, e0 = 0.f, e1 = 0.f;
    for (int h = tid; h < H_; h += 128) {
        float x = row[h];
        float2 ws = *(const float2*)(Ws + 2 * h);
        float2 we = *(const float2*)(We + 2 * h);
        s0 = fmaf(x, ws.x, s0);
        s1 = fmaf(x, ws.y, s1);
        e0 = fmaf(x, we.x, e0);
        e1 = fmaf(x, we.y, e1);
    }
#pragma unroll
    for (int o = 16; o; o >>= 1) {
        s0 += __shfl_down_sync(0xffffffffu, s0, o);
        s1 += __shfl_down_sync(0xffffffffu, s1, o);
        e0 += __shfl_down_sync(0xffffffffu, e0, o);
        e1 += __shfl_down_sync(0xffffffffu, e1, o);
    }
    __shared__ float buf[4][4];
    int w = tid >> 5, lane = tid & 31;
    if (lane == 0) { buf[w][0] = s0; buf[w][1] = s1; buf[w][2] = e0; buf[w][3] = e1; }
    __syncthreads();
    if (tid == 0) {
        s0 = buf[0][0] + buf[1][0] + buf[2][0] + buf[3][0] + bs[0];
        s1 = buf[0][1] + buf[1][1] + buf[2][1] + buf[3][1] + bs[1];
        e0 = buf[0][2] + buf[1][2] + buf[2][2] + buf[3][2] + be[0];
        e1 = buf[0][3] + buf[1][3] + buf[2][3] + buf[3][3] + be[1];
        float mx  = fmaxf(s0, s1);
        float lse = mx + logf(expf(s0 - mx) + expf(s1 - mx));
        g_se[m] = lse - (spos[m] ? s1 : s0);
        mx  = fmaxf(e0, e1);
        lse = mx + logf(expf(e0 - mx) + expf(e1 - mx));
        g_se[M_ + m] = lse - (epos[m] ? e1 : e0);
    }
}

// ---------------- span BCE: 32x32 (i,j) tile, 512 thr = 4 h-quarters x 128 ----
// Each thread: 2(i) x 4(j) outputs = 4 packed gelu chains over its h-quarter.
__global__ void __launch_bounds__(512) span_kernel(
    const int* __restrict__ spanp, const float* __restrict__ w2,
    const float* __restrict__ b2, float* __restrict__ out)
{
    __shared__ __align__(16) float sAt[4][32][34];  // [q][h][i] transposed, pairs 8B-aligned
    __shared__ float sC[4][32][33];                 // [q][j][h]
    __shared__ float sW[4][32];
    __shared__ __align__(16) ull part[3][128][4];   // quarters 1..3 partials (reused as red)
    __shared__ int isLast;

    int tid = threadIdx.x;
    int q = tid >> 7;              // h-quarter 0..3
    int t = tid & 127;
    int ty = t >> 3;               // 0..15 -> i-pair
    int tx = t & 7;                // 0..7  -> j-quad
    int b = blockIdx.z;
    int i0 = blockIdx.y << 5;
    int j0 = blockIdx.x << 5;
    const float* Abase = g_A + (b * L_ + i0) * H_ + q * 192;
    const float* Cbase = g_C + (b * L_ + j0) * H_ + q * 192;

    const GK gk = make_gk();

    int il = ty << 1, jl = tx << 2;
    ull acc0 = 0ULL, acc1 = 0ULL, acc2 = 0ULL, acc3 = 0ULL;

    for (int hc = 0; hc < 192; hc += 32) {
        {
            int row = t >> 2;              // 0..31
            int c8  = (t & 3) << 3;        // 0,8,16,24
            float4 va0 = *(const float4*)(Abase + row * H_ + hc + c8);
            float4 va1 = *(const float4*)(Abase + row * H_ + hc + c8 + 4);
            sAt[q][c8 + 0][row] = va0.x; sAt[q][c8 + 1][row] = va0.y;
            sAt[q][c8 + 2][row] = va0.z; sAt[q][c8 + 3][row] = va0.w;
            sAt[q][c8 + 4][row] = va1.x; sAt[q][c8 + 5][row] = va1.y;
            sAt[q][c8 + 6][row] = va1.z; sAt[q][c8 + 7][row] = va1.w;
            float4 vc0 = *(const float4*)(Cbase + row * H_ + hc + c8);
            float4 vc1 = *(const float4*)(Cbase + row * H_ + hc + c8 + 4);
            sC[q][row][c8 + 0] = vc0.x; sC[q][row][c8 + 1] = vc0.y;
            sC[q][row][c8 + 2] = vc0.z; sC[q][row][c8 + 3] = vc0.w;
            sC[q][row][c8 + 4] = vc1.x; sC[q][row][c8 + 5] = vc1.y;
            sC[q][row][c8 + 6] = vc1.z; sC[q][row][c8 + 7] = vc1.w;
        }
        if (t < 32) sW[q][t] = w2[q * 192 + hc + t];
        __syncthreads();
#pragma unroll 4
        for (int h = 0; h < 32; h++) {
            ull aP = *(const ull*)(&sAt[q][h][il]);   // (a_i0, a_i1)
            ull wd = dup2(sW[q][h]);
            float c0 = sC[q][jl + 0][h];
            float c1 = sC[q][jl + 1][h];
            float c2 = sC[q][jl + 2][h];
            float c3 = sC[q][jl + 3][h];
            acc0 = fma2_(gelu2(add2_(aP, dup2(c0)), gk), wd, acc0);
            acc1 = fma2_(gelu2(add2_(aP, dup2(c1)), gk), wd, acc1);
            acc2 = fma2_(gelu2(add2_(aP, dup2(c2)), gk), wd, acc2);
            acc3 = fma2_(gelu2(add2_(aP, dup2(c3)), gk), wd, acc3);
        }
        __syncthreads();
    }

    if (q) {
        part[q - 1][t][0] = acc0; part[q - 1][t][1] = acc1;
        part[q - 1][t][2] = acc2; part[q - 1][t][3] = acc3;
    }
    __syncthreads();

    float bsum = 0.f;
    if (!q) {
        // fixed-order combine: q0 + q1 + q2 + q3
        acc0 = add2_(add2_(add2_(acc0, part[0][t][0]), part[1][t][0]), part[2][t][0]);
        acc1 = add2_(add2_(add2_(acc1, part[0][t][1]), part[1][t][1]), part[2][t][1]);
        acc2 = add2_(add2_(add2_(acc2, part[0][t][2]), part[1][t][2]), part[2][t][2]);
        acc3 = add2_(add2_(add2_(acc3, part[0][t][3]), part[1][t][3]), part[2][t][3]);
        float b2v = b2[0];
        const int* zb = spanp + b * LL_;
        int i = i0 + il, j = j0 + jl;
        float lg[2][4];
        upk2(acc0, lg[0][0], lg[1][0]);
        upk2(acc1, lg[0][1], lg[1][1]);
        upk2(acc2, lg[0][2], lg[1][2]);
        upk2(acc3, lg[0][3], lg[1][3]);
#pragma unroll
        for (int r = 0; r < 2; r++)
#pragma unroll
            for (int s = 0; s < 4; s++) {
                float sg = lg[r][s] + b2v;
                float z  = (float)zb[(i + r) * L_ + (j + s)];
                bsum += fmaxf(sg, 0.f) - sg * z + log1pf(__expf(-fabsf(sg)));
            }
    }
    __syncthreads();                    // part fully consumed before red reuse

    float* red = reinterpret_cast<float*>(part);
    red[tid] = bsum;
    __syncthreads();
    for (int o = 256; o; o >>= 1) {
        if (tid < o) red[tid] += red[tid + o];
        __syncthreads();
    }
    int bid = (blockIdx.z << 4) + (blockIdx.y << 2) + blockIdx.x;
    if (tid == 0) {
        g_span_partial[bid] = red[0];
        __threadfence();
        unsigned int old = atomicAdd(&g_counter, 1u);
        isLast = (old == 127u);
    }
    __syncthreads();

    if (isLast) {
        __threadfence();
        float se = 0.f;
        for (int v = tid; v < 2 * M_; v += 512) se += g_se[v];
        float sp = (tid < 128) ? g_span_partial[tid] : 0.f;
        red[tid] = se * (1.0f / (float)M_) + sp * (1.0f / (float)(B_ * LL_));
        __syncthreads();
        for (int o = 256; o; o >>= 1) {
            if (tid < o) red[tid] += red[tid + o];
            __syncthreads();
        }
        if (tid == 0) { out[0] = red[0]; g_counter = 0u; }
    }
}

// ---------------- launch ----------------
extern "C" void kernel_launch(void* const* d_in, const int* in_sizes, int n_in,
                              void* d_out, int out_size)
{
    const float* seq   = (const float*)d_in[0];
    const int*   spos  = (const int*)  d_in[1];
    const int*   epos  = (const int*)  d_in[2];
    const int*   spanp = (const int*)  d_in[3];
    const float* Ws    = (const float*)d_in[4];
    const float* bs    = (const float*)d_in[5];
    const float* We    = (const float*)d_in[6];
    const float* be    = (const float*)d_in[7];
    const float* W1    = (const float*)d_in[8];
    const float* b1    = (const float*)d_in[9];
    const float* w2    = (const float*)d_in[10];
    const float* b2    = (const float*)d_in[11];
    float* out = (float*)d_out;

    gemm_kernel<<<dim3(24, 8, 2), 256>>>(seq, W1);
    combine_kernel<<<1536, 256>>>(b1);
    se_kernel<<<M_, 128>>>(seq, Ws, bs, We, be, spos, epos);
    span_kernel<<<dim3(4, 4, 8), 512>>>(spanp, w2, b2, out);
}

// round 9
// speedup vs baseline: 2.0357x; 1.0157x over previous
#include <cuda_runtime.h>
#include <mma.h>
#include <math.h>

using namespace nvcuda;

#define B_  8
#define L_  128
#define H_  768
#define M_  (B_ * L_)      // 1024 rows
#define LL_ (L_ * L_)      // 16384 pairs per batch

// ---------------- scratch (no allocations allowed) ----------------
__device__ float g_Ap[4][M_ * H_];      // k-quarter partials of seq @ W1[:H]
__device__ float g_Cp[4][M_ * H_];      // k-quarter partials of seq @ W1[H:]
__device__ float g_A[M_ * H_];          // combined A + b1
__device__ float g_C[M_ * H_];          // combined C
__device__ float g_lp[3][M_ * L_];      // h-slice partial span logits
__device__ float g_se[2 * M_];          // per-row start/end CE
__device__ float g_span_partial[128];   // per-bce-block BCE partials
__device__ unsigned int g_counter;      // last-block counter (self-resetting)

// ---------------- f32x2 packed helpers ----------------
typedef unsigned long long ull;

__device__ __forceinline__ ull dup2(float v) {
    ull r; asm("mov.b64 %0, {%1, %2};" : "=l"(r) : "f"(v), "f"(v)); return r;
}
__device__ __forceinline__ ull pk2(float lo, float hi) {
    ull r; asm("mov.b64 %0, {%1, %2};" : "=l"(r) : "f"(lo), "f"(hi)); return r;
}
__device__ __forceinline__ void upk2(ull v, float& lo, float& hi) {
    asm("mov.b64 {%0, %1}, %2;" : "=f"(lo), "=f"(hi) : "l"(v));
}
__device__ __forceinline__ ull fma2_(ull a, ull b, ull c) {
    ull d; asm("fma.rn.f32x2 %0, %1, %2, %3;" : "=l"(d) : "l"(a), "l"(b), "l"(c)); return d;
}
__device__ __forceinline__ ull mul2_(ull a, ull b) {
    ull d; asm("mul.rn.f32x2 %0, %1, %2;" : "=l"(d) : "l"(a), "l"(b)); return d;
}
__device__ __forceinline__ ull add2_(ull a, ull b) {
    ull d; asm("add.rn.f32x2 %0, %1, %2;" : "=l"(d) : "l"(a), "l"(b)); return d;
}
__device__ __forceinline__ float rcp_(float x) {
    float r; asm("rcp.approx.f32 %0, %1;" : "=f"(r) : "f"(x)); return r;
}

// hoisted constants for gelu2 (A&S 7.1.28: 1 rcp, no exp)
struct GK {
    ull irt2, one, negone, half, a1, a2, a3, a4, a5, a6;
};
__device__ __forceinline__ GK make_gk() {
    GK k;
    k.irt2   = dup2(0.70710678118654752f);
    k.one    = dup2(1.0f);
    k.negone = dup2(-1.0f);
    k.half   = dup2(0.5f);
    k.a1 = dup2(0.0705230784f);
    k.a2 = dup2(0.0422820123f);
    k.a3 = dup2(0.0092705272f);
    k.a4 = dup2(0.0001520143f);
    k.a5 = dup2(0.0002765672f);
    k.a6 = dup2(0.0000430638f);
    return k;
}

// packed GELU via A&S 7.1.28: erf(z) = 1 - (1+a1 z+...+a6 z^6)^-16, |eps|<=3e-7
__device__ __forceinline__ ull gelu2(ull x, const GK& k) {
    ull ax  = x & 0x7FFFFFFF7FFFFFFFULL;
    ull sgn = x & 0x8000000080000000ULL;
    ull z = mul2_(ax, k.irt2);
    ull u = fma2_(k.a6, z, k.a5);
    u = fma2_(u, z, k.a4);
    u = fma2_(u, z, k.a3);
    u = fma2_(u, z, k.a2);
    u = fma2_(u, z, k.a1);
    u = fma2_(u, z, k.one);
    ull u2  = mul2_(u, u);
    ull u4  = mul2_(u2, u2);
    ull u8  = mul2_(u4, u4);
    ull u16 = mul2_(u8, u8);
    float l, h; upk2(u16, l, h);
    ull r = pk2(rcp_(l), rcp_(h));
    ull erf = fma2_(r, k.negone, k.one);   // 1 - u^-16, in [0,1)
    erf |= sgn;                            // copysign(erf, x)
    ull hx = mul2_(x, k.half);
    return fma2_(hx, erf, hx);
}

// ---------------- tf32 wmma GEMM (k-split x4, register-prefetch pipeline) ----
__global__ void __launch_bounds__(256) gemm_kernel(
    const float* __restrict__ seq, const float* __restrict__ W1)
{
    __shared__ __align__(16) float As[128][36];
    __shared__ __align__(16) float Bs[32][68];

    int tid = threadIdx.x;
    int wid = tid >> 5;
    int wm = wid >> 1;                 // 0..3
    int wn = wid & 1;                  // 0..1
    int m0 = blockIdx.y << 7;          // 8 m-tiles
    int n0 = blockIdx.x << 6;          // 24 n-tiles
    int kz = (int)blockIdx.z * 192;    // k-quarter offset
    int isC = (n0 >= H_);
    const float* Bbase = W1 + (isC ? (H_ * H_ + (n0 - H_)) : n0);

    if (blockIdx.x == 0 && blockIdx.y == 0 && blockIdx.z == 0 && tid == 0) g_counter = 0u;

    wmma::fragment<wmma::accumulator, 16, 16, 8, float> acc[2][2];
#pragma unroll
    for (int i = 0; i < 2; i++)
#pragma unroll
        for (int j = 0; j < 2; j++) wmma::fill_fragment(acc[i][j], 0.0f);

    int a_row = tid >> 1;              // 0..127
    int a_c16 = (tid & 1) << 4;        // 0 or 16
    int b_k   = tid >> 3;              // 0..31
    int b_n8  = (tid & 7) << 3;        // 0..56

    const float* arow = seq + (m0 + a_row) * H_ + kz + a_c16;
    const float* brow = Bbase + (kz + b_k) * H_ + b_n8;

    float4 pa[4], pb[2];
#pragma unroll
    for (int q = 0; q < 4; q++) pa[q] = *(const float4*)(arow + (q << 2));
#pragma unroll
    for (int q = 0; q < 2; q++) pb[q] = *(const float4*)(brow + (q << 2));

    for (int it = 0; it < 6; it++) {
#pragma unroll
        for (int q = 0; q < 4; q++) {
            As[a_row][a_c16 + (q << 2) + 0] = wmma::__float_to_tf32(pa[q].x);
            As[a_row][a_c16 + (q << 2) + 1] = wmma::__float_to_tf32(pa[q].y);
            As[a_row][a_c16 + (q << 2) + 2] = wmma::__float_to_tf32(pa[q].z);
            As[a_row][a_c16 + (q << 2) + 3] = wmma::__float_to_tf32(pa[q].w);
        }
#pragma unroll
        for (int q = 0; q < 2; q++) {
            Bs[b_k][b_n8 + (q << 2) + 0] = wmma::__float_to_tf32(pb[q].x);
            Bs[b_k][b_n8 + (q << 2) + 1] = wmma::__float_to_tf32(pb[q].y);
            Bs[b_k][b_n8 + (q << 2) + 2] = wmma::__float_to_tf32(pb[q].z);
            Bs[b_k][b_n8 + (q << 2) + 3] = wmma::__float_to_tf32(pb[q].w);
        }
        __syncthreads();
        if (it < 5) {
            arow += 32;
            brow += 32 * H_;
#pragma unroll
            for (int q = 0; q < 4; q++) pa[q] = *(const float4*)(arow + (q << 2));
#pragma unroll
            for (int q = 0; q < 2; q++) pb[q] = *(const float4*)(brow + (q << 2));
        }
#pragma unroll
        for (int sk = 0; sk < 4; sk++) {
            wmma::fragment<wmma::matrix_a, 16, 16, 8, wmma::precision::tf32, wmma::row_major> af[2];
            wmma::fragment<wmma::matrix_b, 16, 16, 8, wmma::precision::tf32, wmma::row_major> bf[2];
            wmma::load_matrix_sync(af[0], &As[(wm << 5) +  0][sk << 3], 36);
            wmma::load_matrix_sync(af[1], &As[(wm << 5) + 16][sk << 3], 36);
            wmma::load_matrix_sync(bf[0], &Bs[sk << 3][(wn << 5) +  0], 68);
            wmma::load_matrix_sync(bf[1], &Bs[sk << 3][(wn << 5) + 16], 68);
#pragma unroll
            for (int i = 0; i < 2; i++)
#pragma unroll
                for (int j = 0; j < 2; j++)
                    wmma::mma_sync(acc[i][j], af[i], bf[j], acc[i][j]);
        }
        __syncthreads();
    }

    float* dst = isC ? g_Cp[blockIdx.z] : g_Ap[blockIdx.z];
    int colbase = (isC ? (n0 - H_) : n0) + (wn << 5);
    int rowbase = m0 + (wm << 5);
#pragma unroll
    for (int i = 0; i < 2; i++)
#pragma unroll
        for (int j = 0; j < 2; j++)
            wmma::store_matrix_sync(dst + (rowbase + (i << 4)) * H_ + colbase + (j << 4),
                                    acc[i][j], H_, wmma::mem_row_major);
}

// ---------------- combine k-split partials; fold b1 into A --------------------
__global__ void __launch_bounds__(256) combine_kernel(const float* __restrict__ b1)
{
    int idx = blockIdx.x * 256 + threadIdx.x;
    if (blockIdx.x < 768) {
        int f = idx << 2;
        float4 a0 = *(const float4*)(g_Ap[0] + f);
        float4 a1 = *(const float4*)(g_Ap[1] + f);
        float4 a2 = *(const float4*)(g_Ap[2] + f);
        float4 a3 = *(const float4*)(g_Ap[3] + f);
        float4 bb = *(const float4*)(b1 + (f % H_));
        float4 o;
        o.x = ((a0.x + a1.x) + (a2.x + a3.x)) + bb.x;
        o.y = ((a0.y + a1.y) + (a2.y + a3.y)) + bb.y;
        o.z = ((a0.z + a1.z) + (a2.z + a3.z)) + bb.z;
        o.w = ((a0.w + a1.w) + (a2.w + a3.w)) + bb.w;
        *(float4*)(g_A + f) = o;
    } else {
        int f = (idx - 768 * 256) << 2;
        float4 c0 = *(const float4*)(g_Cp[0] + f);
        float4 c1 = *(const float4*)(g_Cp[1] + f);
        float4 c2 = *(const float4*)(g_Cp[2] + f);
        float4 c3 = *(const float4*)(g_Cp[3] + f);
        float4 o;
        o.x = (c0.x + c1.x) + (c2.x + c3.x);
        o.y = (c0.y + c1.y) + (c2.y + c3.y);
        o.z = (c0.z + c1.z) + (c2.z + c3.z);
        o.w = (c0.w + c1.w) + (c2.w + c3.w);
        *(float4*)(g_C + f) = o;
    }
}

// ---------------- start/end CE: one block per token row ----------------
__global__ void __launch_bounds__(128) se_kernel(
    const float* __restrict__ seq,
    const float* __restrict__ Ws, const float* __restrict__ bs,
    const float* __restrict__ We, const float* __restrict__ be,
    const int* __restrict__ spos, const int* __restrict__ epos)
{
    int m = blockIdx.x;
    int tid = threadIdx.x;
    const float* row = seq + m * H_;
    float s0 = 0.f, s1 = 0.f, e0 = 0.f, e1 = 0.f;
    for (int h = tid; h < H_; h += 128) {
        float x = row[h];
        float2 ws = *(const float2*)(Ws + 2 * h);
        float2 we = *(const float2*)(We + 2 * h);
        s0 = fmaf(x, ws.x, s0);
        s1 = fmaf(x, ws.y, s1);
        e0 = fmaf(x, we.x, e0);
        e1 = fmaf(x, we.y, e1);
    }
#pragma unroll
    for (int o = 16; o; o >>= 1) {
        s0 += __shfl_down_sync(0xffffffffu, s0, o);
        s1 += __shfl_down_sync(0xffffffffu, s1, o);
        e0 += __shfl_down_sync(0xffffffffu, e0, o);
        e1 += __shfl_down_sync(0xffffffffu, e1, o);
    }
    __shared__ float buf[4][4];
    int w = tid >> 5, lane = tid & 31;
    if (lane == 0) { buf[w][0] = s0; buf[w][1] = s1; buf[w][2] = e0; buf[w][3] = e1; }
    __syncthreads();
    if (tid == 0) {
        s0 = buf[0][0] + buf[1][0] + buf[2][0] + buf[3][0] + bs[0];
        s1 = buf[0][1] + buf[1][1] + buf[2][1] + buf[3][1] + bs[1];
        e0 = buf[0][2] + buf[1][2] + buf[2][2] + buf[3][2] + be[0];
        e1 = buf[0][3] + buf[1][3] + buf[2][3] + buf[3][3] + be[1];
        float mx  = fmaxf(s0, s1);
        float lse = mx + logf(expf(s0 - mx) + expf(s1 - mx));
        g_se[m] = lse - (spos[m] ? s1 : s0);
        mx  = fmaxf(e0, e1);
        lse = mx + logf(expf(e0 - mx) + expf(e1 - mx));
        g_se[M_ + m] = lse - (epos[m] ? e1 : e0);
    }
}

// ---------------- span partial logits: 32x32 tile x 1/3 of h ------------------
// grid (4,4,24): z = b*3 + slice. 512 thr = 4 h-quarters (64 h each) x 128.
// Each thread: 2(i) x 4(j) chains. Writes partial logits (no BCE here).
__global__ void __launch_bounds__(512) span_kernel(const float* __restrict__ w2)
{
    __shared__ __align__(16) float sAt[4][16][34];  // [q][h-chunk][i] transposed
    __shared__ __align__(16) ull   sC2[4][32][19];  // [q][j][h-chunk] pre-dup'd
    __shared__ ull   sW2[4][16];
    __shared__ __align__(16) ull part[3][128][4];

    int tid = threadIdx.x;
    int q = tid >> 7;
    int t = tid & 127;
    int ty = t >> 3;
    int tx = t & 7;
    int zb = blockIdx.z;
    int b = zb / 3;
    int s = zb - b * 3;
    int i0 = blockIdx.y << 5;
    int j0 = blockIdx.x << 5;
    int hbase = s * 256 + q * 64;
    const float* Abase = g_A + (b * L_ + i0) * H_ + hbase;
    const float* Cbase = g_C + (b * L_ + j0) * H_ + hbase;
    const float* wbase = w2 + hbase;

    const GK gk = make_gk();

    int il = ty << 1, jl = tx << 2;
    ull acc0 = 0ULL, acc1 = 0ULL, acc2 = 0ULL, acc3 = 0ULL;

    for (int hc = 0; hc < 64; hc += 16) {
        {
            int row = t >> 2;              // 0..31
            int c4  = (t & 3) << 2;        // 0,4,8,12
            float4 va = *(const float4*)(Abase + row * H_ + hc + c4);
            sAt[q][c4 + 0][row] = va.x;
            sAt[q][c4 + 1][row] = va.y;
            sAt[q][c4 + 2][row] = va.z;
            sAt[q][c4 + 3][row] = va.w;
            float4 vc = *(const float4*)(Cbase + row * H_ + hc + c4);
            sC2[q][row][c4 + 0] = dup2(vc.x);
            sC2[q][row][c4 + 1] = dup2(vc.y);
            sC2[q][row][c4 + 2] = dup2(vc.z);
            sC2[q][row][c4 + 3] = dup2(vc.w);
        }
        if (t < 16) sW2[q][t] = dup2(wbase[hc + t]);
        __syncthreads();
#pragma unroll 4
        for (int h = 0; h < 16; h++) {
            ull aP = *(const ull*)(&sAt[q][h][il]);
            ull wd = sW2[q][h];
            ull c0 = sC2[q][jl + 0][h];
            ull c1 = sC2[q][jl + 1][h];
            ull c2 = sC2[q][jl + 2][h];
            ull c3 = sC2[q][jl + 3][h];
            acc0 = fma2_(gelu2(add2_(aP, c0), gk), wd, acc0);
            acc1 = fma2_(gelu2(add2_(aP, c1), gk), wd, acc1);
            acc2 = fma2_(gelu2(add2_(aP, c2), gk), wd, acc2);
            acc3 = fma2_(gelu2(add2_(aP, c3), gk), wd, acc3);
        }
        __syncthreads();
    }

    if (q) {
        part[q - 1][t][0] = acc0; part[q - 1][t][1] = acc1;
        part[q - 1][t][2] = acc2; part[q - 1][t][3] = acc3;
    }
    __syncthreads();

    if (!q) {
        acc0 = add2_(add2_(add2_(acc0, part[0][t][0]), part[1][t][0]), part[2][t][0]);
        acc1 = add2_(add2_(add2_(acc1, part[0][t][1]), part[1][t][1]), part[2][t][1]);
        acc2 = add2_(add2_(add2_(acc2, part[0][t][2]), part[1][t][2]), part[2][t][2]);
        acc3 = add2_(add2_(add2_(acc3, part[0][t][3]), part[1][t][3]), part[2][t][3]);
        float lg[2][4];
        upk2(acc0, lg[0][0], lg[1][0]);
        upk2(acc1, lg[0][1], lg[1][1]);
        upk2(acc2, lg[0][2], lg[1][2]);
        upk2(acc3, lg[0][3], lg[1][3]);
        int i = i0 + il, j = j0 + jl;
        float* dst = g_lp[s] + (b * L_ + i) * L_ + j;
        *(float4*)(dst)      = make_float4(lg[0][0], lg[0][1], lg[0][2], lg[0][3]);
        *(float4*)(dst + L_) = make_float4(lg[1][0], lg[1][1], lg[1][2], lg[1][3]);
    }
}

// ---------------- BCE + final reduction over partial logits -------------------
__global__ void __launch_bounds__(256) bce_kernel(
    const int* __restrict__ spanp, const float* __restrict__ b2,
    float* __restrict__ out)
{
    __shared__ float red[256];
    __shared__ int isLast;
    int tid = threadIdx.x;
    int idx = (blockIdx.x * 256 + tid) << 2;   // 4 logits per thread
    float b2v = b2[0];

    float4 p0 = *(const float4*)(g_lp[0] + idx);
    float4 p1 = *(const float4*)(g_lp[1] + idx);
    float4 p2 = *(const float4*)(g_lp[2] + idx);
    int4   zi = *(const int4*)(spanp + idx);

    float lg[4] = { (p0.x + p1.x) + p2.x + b2v, (p0.y + p1.y) + p2.y + b2v,
                    (p0.z + p1.z) + p2.z + b2v, (p0.w + p1.w) + p2.w + b2v };
    int   zz[4] = { zi.x, zi.y, zi.z, zi.w };
    float bsum = 0.f;
#pragma unroll
    for (int u = 0; u < 4; u++) {
        float sg = lg[u];
        float z  = (float)zz[u];
        bsum += fmaxf(sg, 0.f) - sg * z + log1pf(__expf(-fabsf(sg)));
    }

    red[tid] = bsum;
    __syncthreads();
    for (int o = 128; o; o >>= 1) {
        if (tid < o) red[tid] += red[tid + o];
        __syncthreads();
    }
    if (tid == 0) {
        g_span_partial[blockIdx.x] = red[0];
        __threadfence();
        unsigned int old = atomicAdd(&g_counter, 1u);
        isLast = (old == 127u);
    }
    __syncthreads();

    if (isLast) {
        __threadfence();
        float se = 0.f;
        for (int v = tid; v < 2 * M_; v += 256) se += g_se[v];
        float sp = (tid < 128) ? g_span_partial[tid] : 0.f;
        red[tid] = se * (1.0f / (float)M_) + sp * (1.0f / (float)(B_ * LL_));
        __syncthreads();
        for (int o = 128; o; o >>= 1) {
            if (tid < o) red[tid] += red[tid + o];
            __syncthreads();
        }
        if (tid == 0) { out[0] = red[0]; g_counter = 0u; }
    }
}

// ---------------- launch ----------------
extern "C" void kernel_launch(void* const* d_in, const int* in_sizes, int n_in,
                              void* d_out, int out_size)
{
    const float* seq   = (const float*)d_in[0];
    const int*   spos  = (const int*)  d_in[1];
    const int*   epos  = (const int*)  d_in[2];
    const int*   spanp = (const int*)  d_in[3];
    const float* Ws    = (const float*)d_in[4];
    const float* bs    = (const float*)d_in[5];
    const float* We    = (const float*)d_in[6];
    const float* be    = (const float*)d_in[7];
    const float* W1    = (const float*)d_in[8];
    const float* b1    = (const float*)d_in[9];
    const float* w2    = (const float*)d_in[10];
    const float* b2    = (const float*)d_in[11];
    float* out = (float*)d_out;

    gemm_kernel<<<dim3(24, 8, 4), 256>>>(seq, W1);
    combine_kernel<<<1536, 256>>>(b1);
    se_kernel<<<M_, 128>>>(seq, Ws, bs, We, be, spos, epos);
    span_kernel<<<dim3(4, 4, 24), 512>>>(w2);
    bce_kernel<<<128, 256>>>(spanp, b2, out);
}

// round 10
// speedup vs baseline: 2.2372x; 1.0990x over previous
#include <cuda_runtime.h>
#include <mma.h>
#include <math.h>

using namespace nvcuda;

#define B_  8
#define L_  128
#define H_  768
#define M_  (B_ * L_)      // 1024 rows
#define LL_ (L_ * L_)      // 16384 pairs per batch

// ---------------- scratch (no allocations allowed) ----------------
__device__ float g_Ap[4][M_ * H_];      // k-quarter partials of seq @ W1[:H]
__device__ float g_Cp[4][M_ * H_];      // k-quarter partials of seq @ W1[H:]
__device__ float g_A[M_ * H_];          // combined A + b1
__device__ float g_C[M_ * H_];          // combined C
__device__ float g_lp[3][M_ * L_];      // h-slice partial span logits
__device__ float g_se[2 * M_];          // per-row start/end CE
__device__ float g_span_partial[128];   // per-bce-block BCE partials
__device__ unsigned int g_counter;      // last-block counter (self-resetting)

// ---------------- f32x2 packed helpers ----------------
typedef unsigned long long ull;

__device__ __forceinline__ ull dup2(float v) {
    ull r; asm("mov.b64 %0, {%1, %2};" : "=l"(r) : "f"(v), "f"(v)); return r;
}
__device__ __forceinline__ ull pk2(float lo, float hi) {
    ull r; asm("mov.b64 %0, {%1, %2};" : "=l"(r) : "f"(lo), "f"(hi)); return r;
}
__device__ __forceinline__ void upk2(ull v, float& lo, float& hi) {
    asm("mov.b64 {%0, %1}, %2;" : "=f"(lo), "=f"(hi) : "l"(v));
}
__device__ __forceinline__ ull fma2_(ull a, ull b, ull c) {
    ull d; asm("fma.rn.f32x2 %0, %1, %2, %3;" : "=l"(d) : "l"(a), "l"(b), "l"(c)); return d;
}
__device__ __forceinline__ ull mul2_(ull a, ull b) {
    ull d; asm("mul.rn.f32x2 %0, %1, %2;" : "=l"(d) : "l"(a), "l"(b)); return d;
}
__device__ __forceinline__ ull add2_(ull a, ull b) {
    ull d; asm("add.rn.f32x2 %0, %1, %2;" : "=l"(d) : "l"(a), "l"(b)); return d;
}
__device__ __forceinline__ float rcp_(float x) {
    float r; asm("rcp.approx.f32 %0, %1;" : "=f"(r) : "f"(x)); return r;
}

// hoisted constants for gelu2 (A&S 7.1.27: 4 coeffs, u^-4, 1 rcp, no exp)
struct GK {
    ull irt2, one, half, nhalf, b1, b2, b3, b4;
};
__device__ __forceinline__ GK make_gk() {
    GK k;
    k.irt2  = dup2(0.70710678118654752f);
    k.one   = dup2(1.0f);
    k.half  = dup2(0.5f);
    k.nhalf = dup2(-0.5f);
    k.b1 = dup2(0.278393f);
    k.b2 = dup2(0.230389f);
    k.b3 = dup2(0.000972f);
    k.b4 = dup2(0.078108f);
    return k;
}

// packed GELU via A&S 7.1.27: erf(z) = 1 - (1+b1 z+b2 z^2+b3 z^3+b4 z^4)^-4,
// |eps_erf| <= 5e-4. Sign-free: 0.5x*erf(x/sqrt2) == 0.5|x|*erf(|x|/sqrt2), so
// gelu(x) = 0.5x + 0.5|x| - 0.5|x| * u^-4.   (13 fma-pipe ops, 2 ALU, 2 MUFU)
__device__ __forceinline__ ull gelu2(ull x, const GK& k) {
    ull ax = x & 0x7FFFFFFF7FFFFFFFULL;
    ull z  = mul2_(ax, k.irt2);
    ull u  = fma2_(k.b4, z, k.b3);
    u = fma2_(u, z, k.b2);
    u = fma2_(u, z, k.b1);
    u = fma2_(u, z, k.one);
    ull u2 = mul2_(u, u);
    ull u4 = mul2_(u2, u2);
    float l, h; upk2(u4, l, h);
    ull r   = pk2(rcp_(l), rcp_(h));      // u^-4
    ull xh  = mul2_(x,  k.half);
    ull h2  = fma2_(ax, k.half, xh);      // 0.5x + 0.5|x|
    ull h1n = mul2_(ax, k.nhalf);         // -0.5|x|
    return fma2_(h1n, r, h2);
}

// ---------------- tf32 wmma GEMM (k-split x4, register-prefetch pipeline) ----
__global__ void __launch_bounds__(256) gemm_kernel(
    const float* __restrict__ seq, const float* __restrict__ W1)
{
    __shared__ __align__(16) float As[128][36];
    __shared__ __align__(16) float Bs[32][68];

    int tid = threadIdx.x;
    int wid = tid >> 5;
    int wm = wid >> 1;                 // 0..3
    int wn = wid & 1;                  // 0..1
    int m0 = blockIdx.y << 7;          // 8 m-tiles
    int n0 = blockIdx.x << 6;          // 24 n-tiles
    int kz = (int)blockIdx.z * 192;    // k-quarter offset
    int isC = (n0 >= H_);
    const float* Bbase = W1 + (isC ? (H_ * H_ + (n0 - H_)) : n0);

    if (blockIdx.x == 0 && blockIdx.y == 0 && blockIdx.z == 0 && tid == 0) g_counter = 0u;

    wmma::fragment<wmma::accumulator, 16, 16, 8, float> acc[2][2];
#pragma unroll
    for (int i = 0; i < 2; i++)
#pragma unroll
        for (int j = 0; j < 2; j++) wmma::fill_fragment(acc[i][j], 0.0f);

    int a_row = tid >> 1;              // 0..127
    int a_c16 = (tid & 1) << 4;        // 0 or 16
    int b_k   = tid >> 3;              // 0..31
    int b_n8  = (tid & 7) << 3;        // 0..56

    const float* arow = seq + (m0 + a_row) * H_ + kz + a_c16;
    const float* brow = Bbase + (kz + b_k) * H_ + b_n8;

    float4 pa[4], pb[2];
#pragma unroll
    for (int q = 0; q < 4; q++) pa[q] = *(const float4*)(arow + (q << 2));
#pragma unroll
    for (int q = 0; q < 2; q++) pb[q] = *(const float4*)(brow + (q << 2));

    for (int it = 0; it < 6; it++) {
#pragma unroll
        for (int q = 0; q < 4; q++) {
            As[a_row][a_c16 + (q << 2) + 0] = wmma::__float_to_tf32(pa[q].x);
            As[a_row][a_c16 + (q << 2) + 1] = wmma::__float_to_tf32(pa[q].y);
            As[a_row][a_c16 + (q << 2) + 2] = wmma::__float_to_tf32(pa[q].z);
            As[a_row][a_c16 + (q << 2) + 3] = wmma::__float_to_tf32(pa[q].w);
        }
#pragma unroll
        for (int q = 0; q < 2; q++) {
            Bs[b_k][b_n8 + (q << 2) + 0] = wmma::__float_to_tf32(pb[q].x);
            Bs[b_k][b_n8 + (q << 2) + 1] = wmma::__float_to_tf32(pb[q].y);
            Bs[b_k][b_n8 + (q << 2) + 2] = wmma::__float_to_tf32(pb[q].z);
            Bs[b_k][b_n8 + (q << 2) + 3] = wmma::__float_to_tf32(pb[q].w);
        }
        __syncthreads();
        if (it < 5) {
            arow += 32;
            brow += 32 * H_;
#pragma unroll
            for (int q = 0; q < 4; q++) pa[q] = *(const float4*)(arow + (q << 2));
#pragma unroll
            for (int q = 0; q < 2; q++) pb[q] = *(const float4*)(brow + (q << 2));
        }
#pragma unroll
        for (int sk = 0; sk < 4; sk++) {
            wmma::fragment<wmma::matrix_a, 16, 16, 8, wmma::precision::tf32, wmma::row_major> af[2];
            wmma::fragment<wmma::matrix_b, 16, 16, 8, wmma::precision::tf32, wmma::row_major> bf[2];
            wmma::load_matrix_sync(af[0], &As[(wm << 5) +  0][sk << 3], 36);
            wmma::load_matrix_sync(af[1], &As[(wm << 5) + 16][sk << 3], 36);
            wmma::load_matrix_sync(bf[0], &Bs[sk << 3][(wn << 5) +  0], 68);
            wmma::load_matrix_sync(bf[1], &Bs[sk << 3][(wn << 5) + 16], 68);
#pragma unroll
            for (int i = 0; i < 2; i++)
#pragma unroll
                for (int j = 0; j < 2; j++)
                    wmma::mma_sync(acc[i][j], af[i], bf[j], acc[i][j]);
        }
        __syncthreads();
    }

    float* dst = isC ? g_Cp[blockIdx.z] : g_Ap[blockIdx.z];
    int colbase = (isC ? (n0 - H_) : n0) + (wn << 5);
    int rowbase = m0 + (wm << 5);
#pragma unroll
    for (int i = 0; i < 2; i++)
#pragma unroll
        for (int j = 0; j < 2; j++)
            wmma::store_matrix_sync(dst + (rowbase + (i << 4)) * H_ + colbase + (j << 4),
                                    acc[i][j], H_, wmma::mem_row_major);
}

// ---------------- combine k-split partials; fold b1 into A --------------------
__global__ void __launch_bounds__(256) combine_kernel(const float* __restrict__ b1)
{
    int idx = blockIdx.x * 256 + threadIdx.x;
    if (blockIdx.x < 768) {
        int f = idx << 2;
        float4 a0 = *(const float4*)(g_Ap[0] + f);
        float4 a1 = *(const float4*)(g_Ap[1] + f);
        float4 a2 = *(const float4*)(g_Ap[2] + f);
        float4 a3 = *(const float4*)(g_Ap[3] + f);
        float4 bb = *(const float4*)(b1 + (f % H_));
        float4 o;
        o.x = ((a0.x + a1.x) + (a2.x + a3.x)) + bb.x;
        o.y = ((a0.y + a1.y) + (a2.y + a3.y)) + bb.y;
        o.z = ((a0.z + a1.z) + (a2.z + a3.z)) + bb.z;
        o.w = ((a0.w + a1.w) + (a2.w + a3.w)) + bb.w;
        *(float4*)(g_A + f) = o;
    } else {
        int f = (idx - 768 * 256) << 2;
        float4 c0 = *(const float4*)(g_Cp[0] + f);
        float4 c1 = *(const float4*)(g_Cp[1] + f);
        float4 c2 = *(const float4*)(g_Cp[2] + f);
        float4 c3 = *(const float4*)(g_Cp[3] + f);
        float4 o;
        o.x = (c0.x + c1.x) + (c2.x + c3.x);
        o.y = (c0.y + c1.y) + (c2.y + c3.y);
        o.z = (c0.z + c1.z) + (c2.z + c3.z);
        o.w = (c0.w + c1.w) + (c2.w + c3.w);
        *(float4*)(g_C + f) = o;
    }
}

// ---------------- start/end CE: one block per token row ----------------
__global__ void __launch_bounds__(128) se_kernel(
    const float* __restrict__ seq,
    const float* __restrict__ Ws, const float* __restrict__ bs,
    const float* __restrict__ We, const float* __restrict__ be,
    const int* __restrict__ spos, const int* __restrict__ epos)
{
    int m = blockIdx.x;
    int tid = threadIdx.x;
    const float* row = seq + m * H_;
    float s0 = 0.f, s1 = 0.f, e0 = 0.f, e1 = 0.f;
    for (int h = tid; h < H_; h += 128) {
        float x = row[h];
        float2 ws = *(const float2*)(Ws + 2 * h);
        float2 we = *(const float2*)(We + 2 * h);
        s0 = fmaf(x, ws.x, s0);
        s1 = fmaf(x, ws.y, s1);
        e0 = fmaf(x, we.x, e0);
        e1 = fmaf(x, we.y, e1);
    }
#pragma unroll
    for (int o = 16; o; o >>= 1) {
        s0 += __shfl_down_sync(0xffffffffu, s0, o);
        s1 += __shfl_down_sync(0xffffffffu, s1, o);
        e0 += __shfl_down_sync(0xffffffffu, e0, o);
        e1 += __shfl_down_sync(0xffffffffu, e1, o);
    }
    __shared__ float buf[4][4];
    int w = tid >> 5, lane = tid & 31;
    if (lane == 0) { buf[w][0] = s0; buf[w][1] = s1; buf[w][2] = e0; buf[w][3] = e1; }
    __syncthreads();
    if (tid == 0) {
        s0 = buf[0][0] + buf[1][0] + buf[2][0] + buf[3][0] + bs[0];
        s1 = buf[0][1] + buf[1][1] + buf[2][1] + buf[3][1] + bs[1];
        e0 = buf[0][2] + buf[1][2] + buf[2][2] + buf[3][2] + be[0];
        e1 = buf[0][3] + buf[1][3] + buf[2][3] + buf[3][3] + be[1];
        float mx  = fmaxf(s0, s1);
        float lse = mx + logf(expf(s0 - mx) + expf(s1 - mx));
        g_se[m] = lse - (spos[m] ? s1 : s0);
        mx  = fmaxf(e0, e1);
        lse = mx + logf(expf(e0 - mx) + expf(e1 - mx));
        g_se[M_ + m] = lse - (epos[m] ? e1 : e0);
    }
}

// ---------------- span partial logits: 32x32 tile x 1/3 of h ------------------
// grid (4,4,24): z = b*3 + slice. 512 thr = 4 h-quarters (64 h each) x 128.
// Each thread: 2(i) x 4(j) chains. Writes partial logits (no BCE here).
__global__ void __launch_bounds__(512) span_kernel(const float* __restrict__ w2)
{
    __shared__ __align__(16) float sAt[4][16][34];  // [q][h-chunk][i] transposed
    __shared__ __align__(16) ull   sC2[4][32][19];  // [q][j][h-chunk] pre-dup'd
    __shared__ ull   sW2[4][16];
    __shared__ __align__(16) ull part[3][128][4];

    int tid = threadIdx.x;
    int q = tid >> 7;
    int t = tid & 127;
    int ty = t >> 3;
    int tx = t & 7;
    int zb = blockIdx.z;
    int b = zb / 3;
    int s = zb - b * 3;
    int i0 = blockIdx.y << 5;
    int j0 = blockIdx.x << 5;
    int hbase = s * 256 + q * 64;
    const float* Abase = g_A + (b * L_ + i0) * H_ + hbase;
    const float* Cbase = g_C + (b * L_ + j0) * H_ + hbase;
    const float* wbase = w2 + hbase;

    const GK gk = make_gk();

    int il = ty << 1, jl = tx << 2;
    ull acc0 = 0ULL, acc1 = 0ULL, acc2 = 0ULL, acc3 = 0ULL;

    for (int hc = 0; hc < 64; hc += 16) {
        {
            int row = t >> 2;              // 0..31
            int c4  = (t & 3) << 2;        // 0,4,8,12
            float4 va = *(const float4*)(Abase + row * H_ + hc + c4);
            sAt[q][c4 + 0][row] = va.x;
            sAt[q][c4 + 1][row] = va.y;
            sAt[q][c4 + 2][row] = va.z;
            sAt[q][c4 + 3][row] = va.w;
            float4 vc = *(const float4*)(Cbase + row * H_ + hc + c4);
            sC2[q][row][c4 + 0] = dup2(vc.x);
            sC2[q][row][c4 + 1] = dup2(vc.y);
            sC2[q][row][c4 + 2] = dup2(vc.z);
            sC2[q][row][c4 + 3] = dup2(vc.w);
        }
        if (t < 16) sW2[q][t] = dup2(wbase[hc + t]);
        __syncthreads();
#pragma unroll 4
        for (int h = 0; h < 16; h++) {
            ull aP = *(const ull*)(&sAt[q][h][il]);
            ull wd = sW2[q][h];
            ull c0 = sC2[q][jl + 0][h];
            ull c1 = sC2[q][jl + 1][h];
            ull c2 = sC2[q][jl + 2][h];
            ull c3 = sC2[q][jl + 3][h];
            acc0 = fma2_(gelu2(add2_(aP, c0), gk), wd, acc0);
            acc1 = fma2_(gelu2(add2_(aP, c1), gk), wd, acc1);
            acc2 = fma2_(gelu2(add2_(aP, c2), gk), wd, acc2);
            acc3 = fma2_(gelu2(add2_(aP, c3), gk), wd, acc3);
        }
        __syncthreads();
    }

    if (q) {
        part[q - 1][t][0] = acc0; part[q - 1][t][1] = acc1;
        part[q - 1][t][2] = acc2; part[q - 1][t][3] = acc3;
    }
    __syncthreads();

    if (!q) {
        acc0 = add2_(add2_(add2_(acc0, part[0][t][0]), part[1][t][0]), part[2][t][0]);
        acc1 = add2_(add2_(add2_(acc1, part[0][t][1]), part[1][t][1]), part[2][t][1]);
        acc2 = add2_(add2_(add2_(acc2, part[0][t][2]), part[1][t][2]), part[2][t][2]);
        acc3 = add2_(add2_(add2_(acc3, part[0][t][3]), part[1][t][3]), part[2][t][3]);
        float lg[2][4];
        upk2(acc0, lg[0][0], lg[1][0]);
        upk2(acc1, lg[0][1], lg[1][1]);
        upk2(acc2, lg[0][2], lg[1][2]);
        upk2(acc3, lg[0][3], lg[1][3]);
        int i = i0 + il, j = j0 + jl;
        float* dst = g_lp[s] + (b * L_ + i) * L_ + j;
        *(float4*)(dst)      = make_float4(lg[0][0], lg[0][1], lg[0][2], lg[0][3]);
        *(float4*)(dst + L_) = make_float4(lg[1][0], lg[1][1], lg[1][2], lg[1][3]);
    }
}

// ---------------- BCE + final reduction over partial logits -------------------
__global__ void __launch_bounds__(256) bce_kernel(
    const int* __restrict__ spanp, const float* __restrict__ b2,
    float* __restrict__ out)
{
    __shared__ float red[256];
    __shared__ int isLast;
    int tid = threadIdx.x;
    int idx = (blockIdx.x * 256 + tid) << 2;   // 4 logits per thread
    float b2v = b2[0];

    float4 p0 = *(const float4*)(g_lp[0] + idx);
    float4 p1 = *(const float4*)(g_lp[1] + idx);
    float4 p2 = *(const float4*)(g_lp[2] + idx);
    int4   zi = *(const int4*)(spanp + idx);

    float lg[4] = { (p0.x + p1.x) + p2.x + b2v, (p0.y + p1.y) + p2.y + b2v,
                    (p0.z + p1.z) + p2.z + b2v, (p0.w + p1.w) + p2.w + b2v };
    int   zz[4] = { zi.x, zi.y, zi.z, zi.w };
    float bsum = 0.f;
#pragma unroll
    for (int u = 0; u < 4; u++) {
        float sg = lg[u];
        float z  = (float)zz[u];
        bsum += fmaxf(sg, 0.f) - sg * z + log1pf(__expf(-fabsf(sg)));
    }

    red[tid] = bsum;
    __syncthreads();
    for (int o = 128; o; o >>= 1) {
        if (tid < o) red[tid] += red[tid + o];
        __syncthreads();
    }
    if (tid == 0) {
        g_span_partial[blockIdx.x] = red[0];
        __threadfence();
        unsigned int old = atomicAdd(&g_counter, 1u);
        isLast = (old == 127u);
    }
    __syncthreads();

    if (isLast) {
        __threadfence();
        float se = 0.f;
        for (int v = tid; v < 2 * M_; v += 256) se += g_se[v];
        float sp = (tid < 128) ? g_span_partial[tid] : 0.f;
        red[tid] = se * (1.0f / (float)M_) + sp * (1.0f / (float)(B_ * LL_));
        __syncthreads();
        for (int o = 128; o; o >>= 1) {
            if (tid < o) red[tid] += red[tid + o];
            __syncthreads();
        }
        if (tid == 0) { out[0] = red[0]; g_counter = 0u; }
    }
}

// ---------------- launch ----------------
extern "C" void kernel_launch(void* const* d_in, const int* in_sizes, int n_in,
                              void* d_out, int out_size)
{
    const float* seq   = (const float*)d_in[0];
    const int*   spos  = (const int*)  d_in[1];
    const int*   epos  = (const int*)  d_in[2];
    const int*   spanp = (const int*)  d_in[3];
    const float* Ws    = (const float*)d_in[4];
    const float* bs    = (const float*)d_in[5];
    const float* We    = (const float*)d_in[6];
    const float* be    = (const float*)d_in[7];
    const float* W1    = (const float*)d_in[8];
    const float* b1    = (const float*)d_in[9];
    const float* w2    = (const float*)d_in[10];
    const float* b2    = (const float*)d_in[11];
    float* out = (float*)d_out;

    gemm_kernel<<<dim3(24, 8, 4), 256>>>(seq, W1);
    combine_kernel<<<1536, 256>>>(b1);
    se_kernel<<<M_, 128>>>(seq, Ws, bs, We, be, spos, epos);
    span_kernel<<<dim3(4, 4, 24), 512>>>(w2);
    bce_kernel<<<128, 256>>>(spanp, b2, out);
}